// round 6
// baseline (speedup 1.0000x reference)
#include <cuda_runtime.h>
#include <cuda_bf16.h>

#define BB 16
#define RR 1024
#define TT 512
#define DD 1024
#define HH 1024

// ---------------------------------------------------------------------------
// Scratch (device globals — allocations are forbidden)
// ---------------------------------------------------------------------------
__device__ __nv_bfloat16 g_Wr_h[DD * HH], g_Wr_l[DD * HH];
__device__ __nv_bfloat16 g_Wq_h[DD * HH], g_Wq_l[DD * HH];
__device__ __nv_bfloat16 g_M2_h[DD * DD], g_M2_l[DD * DD];       // M2[d,e] = sum_h Wr[d,h]Wq[e,h]
__device__ __nv_bfloat16 g_rf_h[(size_t)BB * RR * DD], g_rf_l[(size_t)BB * RR * DD];
__device__ __nv_bfloat16 g_qe_h[(size_t)BB * TT * DD], g_qe_l[(size_t)BB * TT * DD];
__device__ __nv_bfloat16 g_Nt_h[(size_t)BB * TT * DD], g_Nt_l[(size_t)BB * TT * DD]; // Nt[b][t,d]
__device__ float         g_scores[(size_t)BB * RR * TT];
__device__ __nv_bfloat16 g_attn_h[(size_t)BB * RR * TT], g_attn_l[(size_t)BB * RR * TT];
__device__ __nv_bfloat16 g_qeT_h[(size_t)BB * DD * TT], g_qeT_l[(size_t)BB * DD * TT];
__device__ float         g_part[(size_t)BB * RR * 8];
__device__ float         g_v[DD];
__device__ float         g_qv[BB * TT];

// ---------------------------------------------------------------------------
// PTX helpers (sm_80-level features only: ldmatrix, cp.async, mma.sync)
// ---------------------------------------------------------------------------
__device__ __forceinline__ unsigned smem_u32(const void* p) {
    unsigned a;
    asm("{ .reg .u64 t; cvta.to.shared.u64 t, %1; cvt.u32.u64 %0, t; }" : "=r"(a) : "l"(p));
    return a;
}

#define CP_ASYNC16(dst, src) \
    asm volatile("cp.async.cg.shared.global [%0], [%1], 16;" :: "r"(dst), "l"(src))
#define CP_COMMIT() asm volatile("cp.async.commit_group;" ::: "memory")
#define CP_WAIT0()  asm volatile("cp.async.wait_group 0;" ::: "memory")
#define CP_WAIT1()  asm volatile("cp.async.wait_group 1;" ::: "memory")

__device__ __forceinline__ void ldsm4(unsigned* r, unsigned addr) {
    asm volatile("ldmatrix.sync.aligned.m8n8.x4.shared.b16 {%0,%1,%2,%3}, [%4];"
                 : "=r"(r[0]), "=r"(r[1]), "=r"(r[2]), "=r"(r[3]) : "r"(addr));
}

__device__ __forceinline__ void mma_bf16(float* c, const unsigned* a, const unsigned* b) {
    asm volatile(
        "mma.sync.aligned.m16n8k16.row.col.f32.bf16.bf16.f32 "
        "{%0,%1,%2,%3}, {%4,%5,%6,%7}, {%8,%9}, {%0,%1,%2,%3};"
        : "+f"(c[0]), "+f"(c[1]), "+f"(c[2]), "+f"(c[3])
        : "r"(a[0]), "r"(a[1]), "r"(a[2]), "r"(a[3]), "r"(b[0]), "r"(b[1]));
}

__device__ __forceinline__ unsigned swz(unsigned off) {
    return off ^ ((off >> 3) & 0x70);
}

// ---------------------------------------------------------------------------
// Split-bf16 tensor-core GEMM:  C[m,n] = sum_k A[m,k]*B[n,k]
// 3 terms: hh + hl + lh. CTA tile 256x128, K chunks of 64 bf16 (SW128),
// double-buffered cp.async. 8 warps (4M x 2N), warp tile 64x64.
// MODE 0: fp32 C.  MODE 1: split hi/lo bf16 C.  MODE 2: fused final scorer —
//   p = sum_n rf*Ws0 + C*Ws1 + rf*C*Ws2 over this CTA's n-slice, one partial
//   per (row, blockIdx.x) written to part[].
// ---------------------------------------------------------------------------
template <int MODE>
__global__ void __launch_bounds__(256, 1) gemm_mma(
    const __nv_bfloat16* __restrict__ A0, const __nv_bfloat16* __restrict__ A1,
    const __nv_bfloat16* __restrict__ B0, const __nv_bfloat16* __restrict__ B1,
    float* __restrict__ Cf, __nv_bfloat16* __restrict__ Ch,
    __nv_bfloat16* __restrict__ Cl,
    const float* __restrict__ rfp, const float* __restrict__ Ws,
    float* __restrict__ part,
    int K, size_t sA, size_t sB, size_t sC, int ldc)
{
    constexpr unsigned TILE_A = 256 * 64 * 2;   // 32 KB per A split tile
    constexpr unsigned TILE_B = 128 * 64 * 2;   // 16 KB per B split tile
    constexpr unsigned STAGE = 2 * TILE_A + 2 * TILE_B;   // 96 KB

    extern __shared__ char smem[];
    const unsigned sbase = smem_u32(smem);

    const int tid = threadIdx.x;
    const int lid = tid & 31;
    const int wid = tid >> 5;
    const int wm = wid & 3;        // M slab (64 rows)
    const int wn = wid >> 2;       // N slab (64 cols)

    const size_t zb = blockIdx.z;
    const __nv_bfloat16* AP[2] = { A0 + zb * sA, A1 + zb * sA };
    const __nv_bfloat16* BP[2] = { B0 + zb * sB, B1 + zb * sB };
    const size_t rm0 = (size_t)blockIdx.y * 256;
    const size_t rn0 = (size_t)blockIdx.x * 128;
    const int NC = K >> 6;

    float c[4][8][4] = {};

    const int al_r  = lid & 15;
    const int al_k  = (lid >> 4) & 1;
    const int bl_r  = (lid & 7) + ((lid >> 4) << 3);
    const int bl_k  = (lid >> 3) & 1;

    auto load_stage = [&](int st, int ck) {
        const unsigned sdst = sbase + (unsigned)st * STAGE;
        const int k0 = ck << 6;
        // A splits: 256 rows x 64 cols
        #pragma unroll
        for (int sp = 0; sp < 2; sp++) {
            const __nv_bfloat16* src = AP[sp];
            #pragma unroll
            for (int i = 0; i < 8; i++) {
                int idx = i * 256 + tid;
                int row = idx >> 3, g = idx & 7;
                const __nv_bfloat16* gs = src + (rm0 + row) * (size_t)K + k0 + g * 8;
                unsigned d = sdst + (unsigned)sp * TILE_A + swz((unsigned)(row * 128 + g * 16));
                CP_ASYNC16(d, gs);
            }
        }
        // B splits: 128 rows x 64 cols
        #pragma unroll
        for (int sp = 0; sp < 2; sp++) {
            const __nv_bfloat16* src = BP[sp];
            #pragma unroll
            for (int i = 0; i < 4; i++) {
                int idx = i * 256 + tid;
                int row = idx >> 3, g = idx & 7;
                const __nv_bfloat16* gs = src + (rn0 + row) * (size_t)K + k0 + g * 8;
                unsigned d = sdst + 2 * TILE_A + (unsigned)sp * TILE_B +
                             swz((unsigned)(row * 128 + g * 16));
                CP_ASYNC16(d, gs);
            }
        }
    };

    load_stage(0, 0);
    CP_COMMIT();

    for (int ck = 0; ck < NC; ck++) {
        if (ck + 1 < NC) {
            load_stage((ck + 1) & 1, ck + 1);
            CP_COMMIT();
            CP_WAIT1();
        } else {
            CP_WAIT0();
        }
        __syncthreads();

        const unsigned sb2 = sbase + (unsigned)(ck & 1) * STAGE;
        #pragma unroll
        for (int ks = 0; ks < 4; ks++) {
            unsigned af[2][4][4];
            unsigned bf[2][8][2];
            #pragma unroll
            for (int sp = 0; sp < 2; sp++) {
                #pragma unroll
                for (int mt = 0; mt < 4; mt++) {
                    unsigned addr = sb2 + (unsigned)sp * TILE_A +
                        swz((unsigned)((wm * 64 + mt * 16 + al_r) * 128 + ks * 32 + al_k * 16));
                    ldsm4(af[sp][mt], addr);
                }
                #pragma unroll
                for (int np = 0; np < 4; np++) {
                    unsigned r[4];
                    unsigned addr = sb2 + 2 * TILE_A + (unsigned)sp * TILE_B +
                        swz((unsigned)((wn * 64 + np * 16 + bl_r) * 128 + ks * 32 + bl_k * 16));
                    ldsm4(r, addr);
                    bf[sp][2 * np][0] = r[0]; bf[sp][2 * np][1] = r[1];
                    bf[sp][2 * np + 1][0] = r[2]; bf[sp][2 * np + 1][1] = r[3];
                }
            }
            // 3 terms: hh, hl, lh
            #pragma unroll
            for (int tm = 0; tm < 3; tm++) {
                const int i = (tm == 2) ? 1 : 0;
                const int j = (tm == 1) ? 1 : 0;
                #pragma unroll
                for (int mt = 0; mt < 4; mt++)
                    #pragma unroll
                    for (int nt = 0; nt < 8; nt++)
                        mma_bf16(c[mt][nt], af[i][mt], bf[j][nt]);
            }
        }
        __syncthreads();
    }

    const int qr = lid >> 2;
    const int qc = (lid & 3) * 2;

    if (MODE == 2) {
        // Fused final: partial dot over this CTA's 128-column d-slice.
        float p[4][2] = {};
        #pragma unroll
        for (int mt = 0; mt < 4; mt++) {
            #pragma unroll
            for (int nt = 0; nt < 8; nt++) {
                int gc = (int)rn0 + wn * 64 + nt * 8 + qc;
                float w0a = Ws[gc],          w0b = Ws[gc + 1];
                float w1a = Ws[DD + gc],     w1b = Ws[DD + gc + 1];
                float w2a = Ws[2 * DD + gc], w2b = Ws[2 * DD + gc + 1];
                #pragma unroll
                for (int half = 0; half < 2; half++) {
                    size_t row = rm0 + wm * 64 + mt * 16 + qr + half * 8;
                    float2 rv = *reinterpret_cast<const float2*>(
                        rfp + (zb * RR + row) * (size_t)DD + gc);
                    float a0 = c[mt][nt][2 * half], a1 = c[mt][nt][2 * half + 1];
                    float acc = p[mt][half];
                    acc = fmaf(rv.x, w0a, acc);
                    acc = fmaf(a0, w1a, acc);
                    acc = fmaf(rv.x * a0, w2a, acc);
                    acc = fmaf(rv.y, w0b, acc);
                    acc = fmaf(a1, w1b, acc);
                    acc = fmaf(rv.y * a1, w2b, acc);
                    p[mt][half] = acc;
                }
            }
        }
        float* sp = reinterpret_cast<float*>(smem);   // [256][2]
        #pragma unroll
        for (int mt = 0; mt < 4; mt++)
            #pragma unroll
            for (int half = 0; half < 2; half++) {
                float v = p[mt][half];
                v += __shfl_xor_sync(0xffffffffu, v, 1);
                v += __shfl_xor_sync(0xffffffffu, v, 2);
                if ((lid & 3) == 0) {
                    int lr = wm * 64 + mt * 16 + qr + half * 8;
                    sp[lr * 2 + wn] = v;
                }
            }
        __syncthreads();
        part[(zb * RR + rm0 + tid) * 8 + blockIdx.x] =
            sp[tid * 2] + sp[tid * 2 + 1];
        return;
    }

    #pragma unroll
    for (int mt = 0; mt < 4; mt++) {
        #pragma unroll
        for (int nt = 0; nt < 8; nt++) {
            size_t gr = rm0 + wm * 64 + mt * 16 + qr;
            int gc = (int)rn0 + wn * 64 + nt * 8 + qc;
            if (MODE == 1) {
                #pragma unroll
                for (int half = 0; half < 2; half++) {
                    float v0 = c[mt][nt][2 * half + 0];
                    float v1 = c[mt][nt][2 * half + 1];
                    size_t o = zb * sC + (gr + half * 8) * (size_t)ldc + gc;
                    __nv_bfloat162 hv, lv;
                    hv.x = __float2bfloat16(v0);
                    hv.y = __float2bfloat16(v1);
                    lv.x = __float2bfloat16(v0 - __bfloat162float(hv.x));
                    lv.y = __float2bfloat16(v1 - __bfloat162float(hv.y));
                    *reinterpret_cast<__nv_bfloat162*>(Ch + o) = hv;
                    *reinterpret_cast<__nv_bfloat162*>(Cl + o) = lv;
                }
            } else {
                #pragma unroll
                for (int half = 0; half < 2; half++) {
                    size_t o = zb * sC + (gr + half * 8) * (size_t)ldc + gc;
                    float2 v = make_float2(c[mt][nt][2 * half], c[mt][nt][2 * half + 1]);
                    *reinterpret_cast<float2*>(Cf + o) = v;
                }
            }
        }
    }
}

// ---------------------------------------------------------------------------
// fp32 -> 2-way bf16 split (elementwise, vectorized)
// ---------------------------------------------------------------------------
__global__ void __launch_bounds__(256) split2_k(
    const float4* __restrict__ x, __nv_bfloat16* __restrict__ h,
    __nv_bfloat16* __restrict__ l, int n4)
{
    for (int i = blockIdx.x * blockDim.x + threadIdx.x; i < n4;
         i += gridDim.x * blockDim.x) {
        float4 v = x[i];
        float a[4] = {v.x, v.y, v.z, v.w};
        __nv_bfloat16 hh[4], ll[4];
        #pragma unroll
        for (int k = 0; k < 4; k++) {
            hh[k] = __float2bfloat16(a[k]);
            ll[k] = __float2bfloat16(a[k] - __bfloat162float(hh[k]));
        }
        __nv_bfloat162 p0, p1;
        p0.x = hh[0]; p0.y = hh[1]; p1.x = hh[2]; p1.y = hh[3];
        reinterpret_cast<__nv_bfloat162*>(h)[2 * i] = p0;
        reinterpret_cast<__nv_bfloat162*>(h)[2 * i + 1] = p1;
        p0.x = ll[0]; p0.y = ll[1]; p1.x = ll[2]; p1.y = ll[3];
        reinterpret_cast<__nv_bfloat162*>(l)[2 * i] = p0;
        reinterpret_cast<__nv_bfloat162*>(l)[2 * i + 1] = p1;
    }
}

// ---------------------------------------------------------------------------
// Batched transpose + 2-way split: src[b,rows,cols] -> dst[b,cols,rows]
// ---------------------------------------------------------------------------
__global__ void tsplit2_k(const float* __restrict__ src,
                          __nv_bfloat16* __restrict__ d0,
                          __nv_bfloat16* __restrict__ d1, int rows, int cols)
{
    __shared__ float tile[32][33];
    int b = blockIdx.z;
    const float* s = src + (size_t)b * rows * cols;
    int c0 = blockIdx.x * 32, r0 = blockIdx.y * 32;
    int tx = threadIdx.x, ty = threadIdx.y;
    #pragma unroll
    for (int k = 0; k < 32; k += 8)
        tile[ty + k][tx] = s[(size_t)(r0 + ty + k) * cols + c0 + tx];
    __syncthreads();
    size_t dbase = (size_t)b * rows * cols;
    #pragma unroll
    for (int k = 0; k < 32; k += 8) {
        int oc = c0 + ty + k;
        float v = tile[tx][ty + k];
        size_t o = dbase + (size_t)oc * rows + r0 + tx;
        __nv_bfloat16 h = __float2bfloat16(v);
        d0[o] = h;
        d1[o] = __float2bfloat16(v - __bfloat162float(h));
    }
}

// ---------------------------------------------------------------------------
// v[d] = sum_h Wq[d,h] * br[h]   (rank-1 bias correction; zero if br==0)
// ---------------------------------------------------------------------------
__global__ void __launch_bounds__(256) matvec_k(
    const float* __restrict__ W, const float* __restrict__ b,
    float* __restrict__ v, int H)
{
    const float* row = W + (size_t)blockIdx.x * H;
    int t = threadIdx.x;
    float p = 0.f;
    for (int h = t * 4; h < H; h += 1024) {
        float4 wv = *reinterpret_cast<const float4*>(row + h);
        float4 bv = *reinterpret_cast<const float4*>(b + h);
        p = fmaf(wv.x, bv.x, p); p = fmaf(wv.y, bv.y, p);
        p = fmaf(wv.z, bv.z, p); p = fmaf(wv.w, bv.w, p);
    }
    __shared__ float red[8];
    #pragma unroll
    for (int o = 16; o; o >>= 1) p += __shfl_xor_sync(0xffffffffu, p, o);
    if ((t & 31) == 0) red[t >> 5] = p;
    __syncthreads();
    if (t == 0) {
        float s = 0.f;
        #pragma unroll
        for (int i = 0; i < 8; i++) s += red[i];
        v[blockIdx.x] = s;
    }
}

// qv[i] = sum_d qe[i,d] * v[d],  i over B*T rows
__global__ void __launch_bounds__(256) rowdot_k(
    const float* __restrict__ qe, const float* __restrict__ v,
    float* __restrict__ qv)
{
    const float* row = qe + (size_t)blockIdx.x * DD;
    int t = threadIdx.x;
    float4 a = *reinterpret_cast<const float4*>(row + t * 4);
    float4 b = *reinterpret_cast<const float4*>(v + t * 4);
    float p = a.x * b.x + a.y * b.y + a.z * b.z + a.w * b.w;
    __shared__ float red[8];
    #pragma unroll
    for (int o = 16; o; o >>= 1) p += __shfl_xor_sync(0xffffffffu, p, o);
    if ((t & 31) == 0) red[t >> 5] = p;
    __syncthreads();
    if (t == 0) {
        float s = 0.f;
        #pragma unroll
        for (int i = 0; i < 8; i++) s += red[i];
        qv[blockIdx.x] = s;
    }
}

// ---------------------------------------------------------------------------
// Row softmax over T=512 (+ per-t additive offset qv) + 2-way bf16 split
// ---------------------------------------------------------------------------
__global__ void __launch_bounds__(256) softmax_split(
    const float* __restrict__ S, const float* __restrict__ qv,
    __nv_bfloat16* __restrict__ Ah, __nv_bfloat16* __restrict__ Al)
{
    const float* row = S + (size_t)blockIdx.x * TT;
    const float* qvb = qv + (blockIdx.x / RR) * TT;
    int t = threadIdx.x;
    float v0 = row[t] + qvb[t];
    float v1 = row[t + 256] + qvb[t + 256];

    __shared__ float red[8];

    float m = fmaxf(v0, v1);
    #pragma unroll
    for (int o = 16; o; o >>= 1) m = fmaxf(m, __shfl_xor_sync(0xffffffffu, m, o));
    if ((t & 31) == 0) red[t >> 5] = m;
    __syncthreads();
    if (t == 0) {
        float x = red[0];
        #pragma unroll
        for (int i = 1; i < 8; i++) x = fmaxf(x, red[i]);
        red[0] = x;
    }
    __syncthreads();
    m = red[0];

    float e0 = expf(v0 - m);
    float e1 = expf(v1 - m);
    float s = e0 + e1;
    #pragma unroll
    for (int o = 16; o; o >>= 1) s += __shfl_xor_sync(0xffffffffu, s, o);
    __syncthreads();
    if ((t & 31) == 0) red[t >> 5] = s;
    __syncthreads();
    if (t == 0) {
        float x = 0.f;
        #pragma unroll
        for (int i = 0; i < 8; i++) x += red[i];
        red[0] = x;
    }
    __syncthreads();
    float inv = 1.0f / red[0];
    size_t base = (size_t)blockIdx.x * TT;

    float a0 = e0 * inv;
    __nv_bfloat16 h0 = __float2bfloat16(a0);
    Ah[base + t] = h0;
    Al[base + t] = __float2bfloat16(a0 - __bfloat162float(h0));

    float a1 = e1 * inv;
    __nv_bfloat16 h1 = __float2bfloat16(a1);
    Ah[base + t + 256] = h1;
    Al[base + t + 256] = __float2bfloat16(a1 - __bfloat162float(h1));
}

// ---------------------------------------------------------------------------
// out[i] = sum of 8 partials + bs
// ---------------------------------------------------------------------------
__global__ void __launch_bounds__(256) reduce8_k(
    const float* __restrict__ part, const float* __restrict__ bs,
    float* __restrict__ out)
{
    int i = blockIdx.x * 256 + threadIdx.x;
    const float4* p4 = reinterpret_cast<const float4*>(part + (size_t)i * 8);
    float4 a = p4[0], b = p4[1];
    out[i] = a.x + a.y + a.z + a.w + b.x + b.y + b.z + b.w + bs[0];
}

// ---------------------------------------------------------------------------
extern "C" void kernel_launch(void* const* d_in, const int* in_sizes, int n_in,
                              void* d_out, int out_size)
{
    const float* region = (const float*)d_in[0];
    const float* query  = (const float*)d_in[1];
    const float* Wr     = (const float*)d_in[2];
    const float* br     = (const float*)d_in[3];
    const float* Wq     = (const float*)d_in[4];
    const float* bq     = (const float*)d_in[5];
    const float* Ws     = (const float*)d_in[6];
    const float* bs     = (const float*)d_in[7];
    float* out = (float*)d_out;
    (void)bq;  // softmax-invariant terms drop out

    __nv_bfloat16 *Wr_h, *Wr_l, *Wq_h, *Wq_l, *M2_h, *M2_l;
    __nv_bfloat16 *rf_h, *rf_l, *qe_h, *qe_l, *Nt_h, *Nt_l;
    __nv_bfloat16 *attn_h, *attn_l, *qeT_h, *qeT_l;
    float *scores, *partb, *v, *qv;
    cudaGetSymbolAddress((void**)&Wr_h, g_Wr_h);
    cudaGetSymbolAddress((void**)&Wr_l, g_Wr_l);
    cudaGetSymbolAddress((void**)&Wq_h, g_Wq_h);
    cudaGetSymbolAddress((void**)&Wq_l, g_Wq_l);
    cudaGetSymbolAddress((void**)&M2_h, g_M2_h);
    cudaGetSymbolAddress((void**)&M2_l, g_M2_l);
    cudaGetSymbolAddress((void**)&rf_h, g_rf_h);
    cudaGetSymbolAddress((void**)&rf_l, g_rf_l);
    cudaGetSymbolAddress((void**)&qe_h, g_qe_h);
    cudaGetSymbolAddress((void**)&qe_l, g_qe_l);
    cudaGetSymbolAddress((void**)&Nt_h, g_Nt_h);
    cudaGetSymbolAddress((void**)&Nt_l, g_Nt_l);
    cudaGetSymbolAddress((void**)&scores, g_scores);
    cudaGetSymbolAddress((void**)&attn_h, g_attn_h);
    cudaGetSymbolAddress((void**)&attn_l, g_attn_l);
    cudaGetSymbolAddress((void**)&qeT_h, g_qeT_h);
    cudaGetSymbolAddress((void**)&qeT_l, g_qeT_l);
    cudaGetSymbolAddress((void**)&partb, g_part);
    cudaGetSymbolAddress((void**)&v, g_v);
    cudaGetSymbolAddress((void**)&qv, g_qv);

    const int SMEM = 2 * (2 * 256 * 64 * 2 + 2 * 128 * 64 * 2);   // 196608
    cudaFuncSetAttribute(gemm_mma<0>, cudaFuncAttributeMaxDynamicSharedMemorySize, SMEM);
    cudaFuncSetAttribute(gemm_mma<1>, cudaFuncAttributeMaxDynamicSharedMemorySize, SMEM);
    cudaFuncSetAttribute(gemm_mma<2>, cudaFuncAttributeMaxDynamicSharedMemorySize, SMEM);

    // 1) splits of weights (K-major over h) and activations
    split2_k<<<512, 256>>>((const float4*)Wr, Wr_h, Wr_l, DD * HH / 4);
    split2_k<<<512, 256>>>((const float4*)Wq, Wq_h, Wq_l, DD * HH / 4);
    split2_k<<<2048, 256>>>((const float4*)region, rf_h, rf_l,
                            (int)((size_t)BB * RR * DD / 4));
    split2_k<<<2048, 256>>>((const float4*)query, qe_h, qe_l,
                            (int)((size_t)BB * TT * DD / 4));
    // 2) M2[d,e] = sum_h Wr[d,h] Wq[e,h]  (e contiguous), split output
    gemm_mma<1><<<dim3(DD / 128, DD / 256, 1), 256, SMEM>>>(
        Wr_h, Wr_l, Wq_h, Wq_l, nullptr, M2_h, M2_l,
        nullptr, nullptr, nullptr, HH, 0, 0, 0, DD);
    // 3) Nt[b][t,d] = sum_e qe[b,t,e] M2[d,e]  (d contiguous), split output
    gemm_mma<1><<<dim3(DD / 128, TT / 256, BB), 256, SMEM>>>(
        qe_h, qe_l, M2_h, M2_l, nullptr, Nt_h, Nt_l,
        nullptr, nullptr, nullptr,
        DD, (size_t)TT * DD, 0, (size_t)TT * DD, DD);
    // 4) rank-1 bias correction: v = Wq@br, qv[b,t] = qe.v
    matvec_k<<<DD, 256>>>(Wq, br, v, HH);
    rowdot_k<<<BB * TT, 256>>>(query, v, qv);
    // 5) scores[b][r,t] = sum_d rf[b,r,d] Nt[b][t,d]  (batched NT)
    gemm_mma<0><<<dim3(TT / 128, RR / 256, BB), 256, SMEM>>>(
        rf_h, rf_l, Nt_h, Nt_l, scores, nullptr, nullptr,
        nullptr, nullptr, nullptr,
        DD, (size_t)RR * DD, (size_t)TT * DD, (size_t)RR * TT, TT);
    // 6) softmax (+qv offset) + split of attn
    softmax_split<<<BB * RR, 256>>>(scores, qv, attn_h, attn_l);
    // 7) query transpose + split (B operand of attend GEMM)
    tsplit2_k<<<dim3(DD / 32, TT / 32, BB), dim3(32, 8)>>>(query, qeT_h, qeT_l, TT, DD);
    // 8) attended GEMM with fused final-scorer epilogue -> partials
    gemm_mma<2><<<dim3(DD / 128, RR / 256, BB), 256, SMEM>>>(
        attn_h, attn_l, qeT_h, qeT_l, nullptr, nullptr, nullptr,
        region, Ws, partb,
        TT, (size_t)RR * TT, (size_t)DD * TT, 0, 0);
    // 9) out = sum of 8 partials + bs
    reduce8_k<<<BB * RR / 256, 256>>>(partb, bs, out);
}

// round 7
// speedup vs baseline: 1.0177x; 1.0177x over previous
#include <cuda_runtime.h>
#include <cuda_bf16.h>

#define BB 16
#define RR 1024
#define TT 512
#define DD 1024
#define HH 1024

// ---------------------------------------------------------------------------
// Scratch (device globals — allocations are forbidden)
// ---------------------------------------------------------------------------
__device__ __nv_bfloat16 g_Wr_h[DD * HH], g_Wr_l[DD * HH];
__device__ __nv_bfloat16 g_Wq_h[DD * HH], g_Wq_l[DD * HH];
__device__ __nv_bfloat16 g_M2_h[DD * DD], g_M2_l[DD * DD];       // M2[d,e] = sum_h Wr[d,h]Wq[e,h]
__device__ __nv_bfloat16 g_rf_h[(size_t)BB * RR * DD], g_rf_l[(size_t)BB * RR * DD];
__device__ __nv_bfloat16 g_rf2_h[(size_t)BB * RR * DD], g_rf2_l[(size_t)BB * RR * DD]; // rf*Ws2
__device__ __nv_bfloat16 g_qe_h[(size_t)BB * TT * DD], g_qe_l[(size_t)BB * TT * DD];
__device__ __nv_bfloat16 g_Nt_h[(size_t)BB * TT * DD], g_Nt_l[(size_t)BB * TT * DD]; // Nt[b][t,d]
__device__ float         g_scores[(size_t)BB * RR * TT];
__device__ float         g_G[(size_t)BB * RR * TT];
__device__ float         g_v[DD];
__device__ float         g_qv[BB * TT];
__device__ float         g_y1[BB * TT];
__device__ float         g_rd0[BB * RR];

// ---------------------------------------------------------------------------
// PTX helpers (sm_80-level features only: ldmatrix, cp.async, mma.sync)
// ---------------------------------------------------------------------------
__device__ __forceinline__ unsigned smem_u32(const void* p) {
    unsigned a;
    asm("{ .reg .u64 t; cvta.to.shared.u64 t, %1; cvt.u32.u64 %0, t; }" : "=r"(a) : "l"(p));
    return a;
}

#define CP_ASYNC16(dst, src) \
    asm volatile("cp.async.cg.shared.global [%0], [%1], 16;" :: "r"(dst), "l"(src))
#define CP_COMMIT() asm volatile("cp.async.commit_group;" ::: "memory")
#define CP_WAIT0()  asm volatile("cp.async.wait_group 0;" ::: "memory")
#define CP_WAIT1()  asm volatile("cp.async.wait_group 1;" ::: "memory")

__device__ __forceinline__ void ldsm4(unsigned* r, unsigned addr) {
    asm volatile("ldmatrix.sync.aligned.m8n8.x4.shared.b16 {%0,%1,%2,%3}, [%4];"
                 : "=r"(r[0]), "=r"(r[1]), "=r"(r[2]), "=r"(r[3]) : "r"(addr));
}

__device__ __forceinline__ void mma_bf16(float* c, const unsigned* a, const unsigned* b) {
    asm volatile(
        "mma.sync.aligned.m16n8k16.row.col.f32.bf16.bf16.f32 "
        "{%0,%1,%2,%3}, {%4,%5,%6,%7}, {%8,%9}, {%0,%1,%2,%3};"
        : "+f"(c[0]), "+f"(c[1]), "+f"(c[2]), "+f"(c[3])
        : "r"(a[0]), "r"(a[1]), "r"(a[2]), "r"(a[3]), "r"(b[0]), "r"(b[1]));
}

__device__ __forceinline__ unsigned swz(unsigned off) {
    return off ^ ((off >> 3) & 0x70);
}

// ---------------------------------------------------------------------------
// Split-bf16 tensor-core GEMM:  C[m,n] = sum_k A[m,k]*B[n,k]
// 3 terms: hh + hl + lh. CTA tile 128x128, K chunks of 64 bf16 (SW128),
// double-buffered cp.async. 8 warps (4M x 2N), warp tile 32x64.
// MODE 0: fp32 C.  MODE 1: split hi/lo bf16 C.
// ---------------------------------------------------------------------------
template <int MODE>
__global__ void __launch_bounds__(256) gemm_mma(
    const __nv_bfloat16* __restrict__ A0, const __nv_bfloat16* __restrict__ A1,
    const __nv_bfloat16* __restrict__ B0, const __nv_bfloat16* __restrict__ B1,
    float* __restrict__ Cf, __nv_bfloat16* __restrict__ Ch,
    __nv_bfloat16* __restrict__ Cl,
    int K, size_t sA, size_t sB, size_t sC, int ldc)
{
    constexpr unsigned TILE = 128 * 64 * 2;   // 16 KB per operand tile
    constexpr unsigned STAGE = 4 * TILE;      // Ah, Al, Bh, Bl

    extern __shared__ char smem[];
    const unsigned sbase = smem_u32(smem);

    const int tid = threadIdx.x;
    const int lid = tid & 31;
    const int wid = tid >> 5;
    const int wm = wid & 3;        // M slab (32 rows)
    const int wn = wid >> 2;       // N slab (64 cols)

    const size_t zb = blockIdx.z;
    const __nv_bfloat16* AP[2] = { A0 + zb * sA, A1 + zb * sA };
    const __nv_bfloat16* BP[2] = { B0 + zb * sB, B1 + zb * sB };
    const size_t rm0 = (size_t)blockIdx.y * 128;
    const size_t rn0 = (size_t)blockIdx.x * 128;
    const int NC = K >> 6;

    float c[2][8][4] = {};

    const int al_r  = lid & 15;
    const int al_k  = (lid >> 4) & 1;
    const int bl_r  = (lid & 7) + ((lid >> 4) << 3);
    const int bl_k  = (lid >> 3) & 1;

    auto load_stage = [&](int st, int ck) {
        const unsigned sdst = sbase + (unsigned)st * STAGE;
        const int k0 = ck << 6;
        #pragma unroll
        for (int t4 = 0; t4 < 4; t4++) {
            const __nv_bfloat16* src = (t4 < 2) ? AP[t4] : BP[t4 - 2];
            const size_t r0 = (t4 < 2) ? rm0 : rn0;
            #pragma unroll
            for (int i = 0; i < 4; i++) {
                int idx = i * 256 + tid;
                int row = idx >> 3, g = idx & 7;
                const __nv_bfloat16* gs = src + (r0 + row) * (size_t)K + k0 + g * 8;
                unsigned d = sdst + (unsigned)t4 * TILE + swz((unsigned)(row * 128 + g * 16));
                CP_ASYNC16(d, gs);
            }
        }
    };

    load_stage(0, 0);
    CP_COMMIT();

    for (int ck = 0; ck < NC; ck++) {
        if (ck + 1 < NC) {
            load_stage((ck + 1) & 1, ck + 1);
            CP_COMMIT();
            CP_WAIT1();
        } else {
            CP_WAIT0();
        }
        __syncthreads();

        const unsigned sb2 = sbase + (unsigned)(ck & 1) * STAGE;
        #pragma unroll
        for (int ks = 0; ks < 4; ks++) {
            unsigned af[2][2][4];
            unsigned bf[2][8][2];
            #pragma unroll
            for (int sp = 0; sp < 2; sp++) {
                #pragma unroll
                for (int mt = 0; mt < 2; mt++) {
                    unsigned addr = sb2 + (unsigned)sp * TILE +
                        swz((unsigned)((wm * 32 + mt * 16 + al_r) * 128 + ks * 32 + al_k * 16));
                    ldsm4(af[sp][mt], addr);
                }
                #pragma unroll
                for (int np = 0; np < 4; np++) {
                    unsigned r[4];
                    unsigned addr = sb2 + (unsigned)(2 + sp) * TILE +
                        swz((unsigned)((wn * 64 + np * 16 + bl_r) * 128 + ks * 32 + bl_k * 16));
                    ldsm4(r, addr);
                    bf[sp][2 * np][0] = r[0]; bf[sp][2 * np][1] = r[1];
                    bf[sp][2 * np + 1][0] = r[2]; bf[sp][2 * np + 1][1] = r[3];
                }
            }
            // 3 terms: hh, hl, lh
            #pragma unroll
            for (int tm = 0; tm < 3; tm++) {
                const int i = (tm == 2) ? 1 : 0;
                const int j = (tm == 1) ? 1 : 0;
                #pragma unroll
                for (int mt = 0; mt < 2; mt++)
                    #pragma unroll
                    for (int nt = 0; nt < 8; nt++)
                        mma_bf16(c[mt][nt], af[i][mt], bf[j][nt]);
            }
        }
        __syncthreads();
    }

    const int qr = lid >> 2;
    const int qc = (lid & 3) * 2;
    #pragma unroll
    for (int mt = 0; mt < 2; mt++) {
        #pragma unroll
        for (int nt = 0; nt < 8; nt++) {
            size_t gr = rm0 + wm * 32 + mt * 16 + qr;
            int gc = (int)rn0 + wn * 64 + nt * 8 + qc;
            if (MODE == 1) {
                #pragma unroll
                for (int half = 0; half < 2; half++) {
                    float v0 = c[mt][nt][2 * half + 0];
                    float v1 = c[mt][nt][2 * half + 1];
                    size_t o = zb * sC + (gr + half * 8) * (size_t)ldc + gc;
                    __nv_bfloat162 hv, lv;
                    hv.x = __float2bfloat16(v0);
                    hv.y = __float2bfloat16(v1);
                    lv.x = __float2bfloat16(v0 - __bfloat162float(hv.x));
                    lv.y = __float2bfloat16(v1 - __bfloat162float(hv.y));
                    *reinterpret_cast<__nv_bfloat162*>(Ch + o) = hv;
                    *reinterpret_cast<__nv_bfloat162*>(Cl + o) = lv;
                }
            } else {
                #pragma unroll
                for (int half = 0; half < 2; half++) {
                    size_t o = zb * sC + (gr + half * 8) * (size_t)ldc + gc;
                    float2 v = make_float2(c[mt][nt][2 * half], c[mt][nt][2 * half + 1]);
                    *reinterpret_cast<float2*>(Cf + o) = v;
                }
            }
        }
    }
}

// ---------------------------------------------------------------------------
// fp32 -> 2-way bf16 split (elementwise, vectorized)
// ---------------------------------------------------------------------------
__global__ void __launch_bounds__(256) split2_k(
    const float4* __restrict__ x, __nv_bfloat16* __restrict__ h,
    __nv_bfloat16* __restrict__ l, int n4)
{
    for (int i = blockIdx.x * blockDim.x + threadIdx.x; i < n4;
         i += gridDim.x * blockDim.x) {
        float4 v = x[i];
        float a[4] = {v.x, v.y, v.z, v.w};
        __nv_bfloat16 hh[4], ll[4];
        #pragma unroll
        for (int k = 0; k < 4; k++) {
            hh[k] = __float2bfloat16(a[k]);
            ll[k] = __float2bfloat16(a[k] - __bfloat162float(hh[k]));
        }
        __nv_bfloat162 p0, p1;
        p0.x = hh[0]; p0.y = hh[1]; p1.x = hh[2]; p1.y = hh[3];
        reinterpret_cast<__nv_bfloat162*>(h)[2 * i] = p0;
        reinterpret_cast<__nv_bfloat162*>(h)[2 * i + 1] = p1;
        p0.x = ll[0]; p0.y = ll[1]; p1.x = ll[2]; p1.y = ll[3];
        reinterpret_cast<__nv_bfloat162*>(l)[2 * i] = p0;
        reinterpret_cast<__nv_bfloat162*>(l)[2 * i + 1] = p1;
    }
}

// ---------------------------------------------------------------------------
// region -> split(rf) and split(rf * Ws2[d])  (d = elem index mod D)
// ---------------------------------------------------------------------------
__global__ void __launch_bounds__(256) split_rf_k(
    const float4* __restrict__ x, const float* __restrict__ Ws2,
    __nv_bfloat16* __restrict__ h, __nv_bfloat16* __restrict__ l,
    __nv_bfloat16* __restrict__ h2, __nv_bfloat16* __restrict__ l2, int n4)
{
    for (int i = blockIdx.x * blockDim.x + threadIdx.x; i < n4;
         i += gridDim.x * blockDim.x) {
        float4 v = x[i];
        int d = (i * 4) & (DD - 1);
        float4 w = *reinterpret_cast<const float4*>(Ws2 + d);
        float a[4] = {v.x, v.y, v.z, v.w};
        float b[4] = {v.x * w.x, v.y * w.y, v.z * w.z, v.w * w.w};
        __nv_bfloat162 p0, p1;
        __nv_bfloat16 t0, t1;
        t0 = __float2bfloat16(a[0]); t1 = __float2bfloat16(a[1]);
        p0.x = t0; p0.y = t1;
        p1.x = __float2bfloat16(a[2]); p1.y = __float2bfloat16(a[3]);
        reinterpret_cast<__nv_bfloat162*>(h)[2 * i] = p0;
        reinterpret_cast<__nv_bfloat162*>(h)[2 * i + 1] = p1;
        __nv_bfloat162 q0, q1;
        q0.x = __float2bfloat16(a[0] - __bfloat162float(p0.x));
        q0.y = __float2bfloat16(a[1] - __bfloat162float(p0.y));
        q1.x = __float2bfloat16(a[2] - __bfloat162float(p1.x));
        q1.y = __float2bfloat16(a[3] - __bfloat162float(p1.y));
        reinterpret_cast<__nv_bfloat162*>(l)[2 * i] = q0;
        reinterpret_cast<__nv_bfloat162*>(l)[2 * i + 1] = q1;
        p0.x = __float2bfloat16(b[0]); p0.y = __float2bfloat16(b[1]);
        p1.x = __float2bfloat16(b[2]); p1.y = __float2bfloat16(b[3]);
        reinterpret_cast<__nv_bfloat162*>(h2)[2 * i] = p0;
        reinterpret_cast<__nv_bfloat162*>(h2)[2 * i + 1] = p1;
        q0.x = __float2bfloat16(b[0] - __bfloat162float(p0.x));
        q0.y = __float2bfloat16(b[1] - __bfloat162float(p0.y));
        q1.x = __float2bfloat16(b[2] - __bfloat162float(p1.x));
        q1.y = __float2bfloat16(b[3] - __bfloat162float(p1.y));
        reinterpret_cast<__nv_bfloat162*>(l2)[2 * i] = q0;
        reinterpret_cast<__nv_bfloat162*>(l2)[2 * i + 1] = q1;
    }
}

// ---------------------------------------------------------------------------
// v[d] = sum_h Wq[d,h] * br[h]
// ---------------------------------------------------------------------------
__global__ void __launch_bounds__(256) matvec_k(
    const float* __restrict__ W, const float* __restrict__ b,
    float* __restrict__ v, int H)
{
    const float* row = W + (size_t)blockIdx.x * H;
    int t = threadIdx.x;
    float p = 0.f;
    for (int h = t * 4; h < H; h += 1024) {
        float4 wv = *reinterpret_cast<const float4*>(row + h);
        float4 bv = *reinterpret_cast<const float4*>(b + h);
        p = fmaf(wv.x, bv.x, p); p = fmaf(wv.y, bv.y, p);
        p = fmaf(wv.z, bv.z, p); p = fmaf(wv.w, bv.w, p);
    }
    __shared__ float red[8];
    #pragma unroll
    for (int o = 16; o; o >>= 1) p += __shfl_xor_sync(0xffffffffu, p, o);
    if ((t & 31) == 0) red[t >> 5] = p;
    __syncthreads();
    if (t == 0) {
        float s = 0.f;
        #pragma unroll
        for (int i = 0; i < 8; i++) s += red[i];
        v[blockIdx.x] = s;
    }
}

// Dual row-dot: qv[i] = row.v ; y1[i] = row.w1   (rows of DD)
__global__ void __launch_bounds__(256) rowdot2_k(
    const float* __restrict__ X, const float* __restrict__ v,
    const float* __restrict__ w1, float* __restrict__ qv,
    float* __restrict__ y1)
{
    const float* row = X + (size_t)blockIdx.x * DD;
    int t = threadIdx.x;
    float4 a = *reinterpret_cast<const float4*>(row + t * 4);
    float4 b = *reinterpret_cast<const float4*>(v + t * 4);
    float4 c = *reinterpret_cast<const float4*>(w1 + t * 4);
    float p = a.x * b.x + a.y * b.y + a.z * b.z + a.w * b.w;
    float q = a.x * c.x + a.y * c.y + a.z * c.z + a.w * c.w;
    __shared__ float red[16];
    #pragma unroll
    for (int o = 16; o; o >>= 1) {
        p += __shfl_xor_sync(0xffffffffu, p, o);
        q += __shfl_xor_sync(0xffffffffu, q, o);
    }
    if ((t & 31) == 0) { red[t >> 5] = p; red[8 + (t >> 5)] = q; }
    __syncthreads();
    if (t == 0) {
        float s = 0.f, s2 = 0.f;
        #pragma unroll
        for (int i = 0; i < 8; i++) { s += red[i]; s2 += red[8 + i]; }
        qv[blockIdx.x] = s;
        y1[blockIdx.x] = s2;
    }
}

// Single row-dot: rd0[i] = row.w0
__global__ void __launch_bounds__(256) rowdot1_k(
    const float* __restrict__ X, const float* __restrict__ w0,
    float* __restrict__ rd0)
{
    const float* row = X + (size_t)blockIdx.x * DD;
    int t = threadIdx.x;
    float4 a = *reinterpret_cast<const float4*>(row + t * 4);
    float4 b = *reinterpret_cast<const float4*>(w0 + t * 4);
    float p = a.x * b.x + a.y * b.y + a.z * b.z + a.w * b.w;
    __shared__ float red[8];
    #pragma unroll
    for (int o = 16; o; o >>= 1) p += __shfl_xor_sync(0xffffffffu, p, o);
    if ((t & 31) == 0) red[t >> 5] = p;
    __syncthreads();
    if (t == 0) {
        float s = 0.f;
        #pragma unroll
        for (int i = 0; i < 8; i++) s += red[i];
        rd0[blockIdx.x] = s;
    }
}

// ---------------------------------------------------------------------------
// Fused softmax + weighted reduction:
// out[b,r] = rd0[b,r] + sum_t softmax(scores[b,r,:]+qv[b,:])[t] * (y1[b,t]+G[b,r,t]) + bs
// ---------------------------------------------------------------------------
__global__ void __launch_bounds__(256) softmax_out(
    const float* __restrict__ S, const float* __restrict__ G,
    const float* __restrict__ qv, const float* __restrict__ y1,
    const float* __restrict__ rd0, const float* __restrict__ bs,
    float* __restrict__ out)
{
    size_t rowi = blockIdx.x;
    const float* row = S + rowi * TT;
    const float* grow = G + rowi * TT;
    size_t boff = (rowi / RR) * TT;
    int t = threadIdx.x;
    float v0 = row[t] + qv[boff + t];
    float v1 = row[t + 256] + qv[boff + t + 256];

    __shared__ float red[16];

    float m = fmaxf(v0, v1);
    #pragma unroll
    for (int o = 16; o; o >>= 1) m = fmaxf(m, __shfl_xor_sync(0xffffffffu, m, o));
    if ((t & 31) == 0) red[t >> 5] = m;
    __syncthreads();
    if (t == 0) {
        float x = red[0];
        #pragma unroll
        for (int i = 1; i < 8; i++) x = fmaxf(x, red[i]);
        red[0] = x;
    }
    __syncthreads();
    m = red[0];
    __syncthreads();

    float e0 = expf(v0 - m);
    float e1 = expf(v1 - m);
    float den = e0 + e1;
    float num = e0 * (y1[boff + t] + grow[t]) +
                e1 * (y1[boff + t + 256] + grow[t + 256]);
    #pragma unroll
    for (int o = 16; o; o >>= 1) {
        den += __shfl_xor_sync(0xffffffffu, den, o);
        num += __shfl_xor_sync(0xffffffffu, num, o);
    }
    if ((t & 31) == 0) { red[t >> 5] = den; red[8 + (t >> 5)] = num; }
    __syncthreads();
    if (t == 0) {
        float sd = 0.f, sn = 0.f;
        #pragma unroll
        for (int i = 0; i < 8; i++) { sd += red[i]; sn += red[8 + i]; }
        out[rowi] = rd0[rowi] + sn / sd + bs[0];
    }
}

// ---------------------------------------------------------------------------
extern "C" void kernel_launch(void* const* d_in, const int* in_sizes, int n_in,
                              void* d_out, int out_size)
{
    const float* region = (const float*)d_in[0];
    const float* query  = (const float*)d_in[1];
    const float* Wr     = (const float*)d_in[2];
    const float* br     = (const float*)d_in[3];
    const float* Wq     = (const float*)d_in[4];
    const float* bq     = (const float*)d_in[5];
    const float* Ws     = (const float*)d_in[6];
    const float* bs     = (const float*)d_in[7];
    float* out = (float*)d_out;
    (void)bq;  // softmax-invariant terms drop out

    __nv_bfloat16 *Wr_h, *Wr_l, *Wq_h, *Wq_l, *M2_h, *M2_l;
    __nv_bfloat16 *rf_h, *rf_l, *rf2_h, *rf2_l, *qe_h, *qe_l, *Nt_h, *Nt_l;
    float *scores, *G, *v, *qv, *y1, *rd0;
    cudaGetSymbolAddress((void**)&Wr_h, g_Wr_h);
    cudaGetSymbolAddress((void**)&Wr_l, g_Wr_l);
    cudaGetSymbolAddress((void**)&Wq_h, g_Wq_h);
    cudaGetSymbolAddress((void**)&Wq_l, g_Wq_l);
    cudaGetSymbolAddress((void**)&M2_h, g_M2_h);
    cudaGetSymbolAddress((void**)&M2_l, g_M2_l);
    cudaGetSymbolAddress((void**)&rf_h, g_rf_h);
    cudaGetSymbolAddress((void**)&rf_l, g_rf_l);
    cudaGetSymbolAddress((void**)&rf2_h, g_rf2_h);
    cudaGetSymbolAddress((void**)&rf2_l, g_rf2_l);
    cudaGetSymbolAddress((void**)&qe_h, g_qe_h);
    cudaGetSymbolAddress((void**)&qe_l, g_qe_l);
    cudaGetSymbolAddress((void**)&Nt_h, g_Nt_h);
    cudaGetSymbolAddress((void**)&Nt_l, g_Nt_l);
    cudaGetSymbolAddress((void**)&scores, g_scores);
    cudaGetSymbolAddress((void**)&G, g_G);
    cudaGetSymbolAddress((void**)&v, g_v);
    cudaGetSymbolAddress((void**)&qv, g_qv);
    cudaGetSymbolAddress((void**)&y1, g_y1);
    cudaGetSymbolAddress((void**)&rd0, g_rd0);

    const int SMEM = 2 * 4 * 16384;   // 131072
    cudaFuncSetAttribute(gemm_mma<0>, cudaFuncAttributeMaxDynamicSharedMemorySize, SMEM);
    cudaFuncSetAttribute(gemm_mma<1>, cudaFuncAttributeMaxDynamicSharedMemorySize, SMEM);

    // 1) splits: weights (K-major over h), query, region (+ region*Ws2)
    split2_k<<<512, 256>>>((const float4*)Wr, Wr_h, Wr_l, DD * HH / 4);
    split2_k<<<512, 256>>>((const float4*)Wq, Wq_h, Wq_l, DD * HH / 4);
    split2_k<<<2048, 256>>>((const float4*)query, qe_h, qe_l,
                            (int)((size_t)BB * TT * DD / 4));
    split_rf_k<<<2048, 256>>>((const float4*)region, Ws + 2 * DD,
                              rf_h, rf_l, rf2_h, rf2_l,
                              (int)((size_t)BB * RR * DD / 4));
    // 2) M2[d,e] = sum_h Wr[d,h] Wq[e,h]  (e contiguous), split output
    gemm_mma<1><<<dim3(DD / 128, DD / 128, 1), 256, SMEM>>>(
        Wr_h, Wr_l, Wq_h, Wq_l, nullptr, M2_h, M2_l, HH, 0, 0, 0, DD);
    // 3) Nt[b][t,d] = sum_e qe[b,t,e] M2[d,e]  (d contiguous), split output
    gemm_mma<1><<<dim3(DD / 128, TT / 128, BB), 256, SMEM>>>(
        qe_h, qe_l, M2_h, M2_l, nullptr, Nt_h, Nt_l,
        DD, (size_t)TT * DD, 0, (size_t)TT * DD, DD);
    // 4) small dots: v = Wq@br; (qv, y1) per query row; rd0 per region row
    matvec_k<<<DD, 256>>>(Wq, br, v, HH);
    rowdot2_k<<<BB * TT, 256>>>(query, v, Ws + DD, qv, y1);
    rowdot1_k<<<BB * RR, 256>>>(region, Ws, rd0);
    // 5) scores[b][r,t] = sum_d rf[b,r,d] Nt[b][t,d]  (batched NT)
    gemm_mma<0><<<dim3(TT / 128, RR / 128, BB), 256, SMEM>>>(
        rf_h, rf_l, Nt_h, Nt_l, scores, nullptr, nullptr,
        DD, (size_t)RR * DD, (size_t)TT * DD, (size_t)RR * TT, TT);
    // 6) G[b][r,t] = sum_d rf2[b,r,d] qe[b,t,d]  (batched NT)
    gemm_mma<0><<<dim3(TT / 128, RR / 128, BB), 256, SMEM>>>(
        rf2_h, rf2_l, qe_h, qe_l, G, nullptr, nullptr,
        DD, (size_t)RR * DD, (size_t)TT * DD, (size_t)RR * TT, TT);
    // 7) fused softmax + weighted sum + final output
    softmax_out<<<BB * RR, 256>>>(scores, G, qv, y1, rd0, bs, out);
}

// round 8
// speedup vs baseline: 1.0887x; 1.0697x over previous
#include <cuda_runtime.h>
#include <cuda_bf16.h>

#define BB 16
#define RR 1024
#define TT 512
#define DD 1024
#define HH 1024

// ---------------------------------------------------------------------------
// Scratch (device globals — allocations are forbidden)
// ---------------------------------------------------------------------------
__device__ __nv_bfloat16 g_Wr_h[DD * HH], g_Wr_l[DD * HH];
__device__ __nv_bfloat16 g_Wq_h[DD * HH], g_Wq_l[DD * HH];
__device__ __nv_bfloat16 g_M2_h[DD * DD], g_M2_l[DD * DD];       // M2[d,e] = sum_h Wr[d,h]Wq[e,h]
__device__ __nv_bfloat16 g_rf_h[(size_t)BB * RR * DD], g_rf_l[(size_t)BB * RR * DD];
__device__ __nv_bfloat16 g_qe_h[(size_t)BB * TT * DD], g_qe_l[(size_t)BB * TT * DD];
__device__ __nv_bfloat16 g_qe2_h[(size_t)BB * TT * DD], g_qe2_l[(size_t)BB * TT * DD]; // qe*Ws2
__device__ __nv_bfloat16 g_Nt_h[(size_t)BB * TT * DD], g_Nt_l[(size_t)BB * TT * DD];   // Nt[b][t,d]
__device__ float         g_scores[(size_t)BB * RR * TT];
__device__ float         g_G[(size_t)BB * RR * TT];
__device__ float         g_v[DD];
__device__ float         g_qv[BB * TT];
__device__ float         g_y1[BB * TT];
__device__ float         g_rd0[BB * RR];

// ---------------------------------------------------------------------------
// PTX helpers (sm_80-level features only: ldmatrix, cp.async, mma.sync)
// ---------------------------------------------------------------------------
__device__ __forceinline__ unsigned smem_u32(const void* p) {
    unsigned a;
    asm("{ .reg .u64 t; cvta.to.shared.u64 t, %1; cvt.u32.u64 %0, t; }" : "=r"(a) : "l"(p));
    return a;
}

#define CP_ASYNC16(dst, src) \
    asm volatile("cp.async.cg.shared.global [%0], [%1], 16;" :: "r"(dst), "l"(src))
#define CP_COMMIT() asm volatile("cp.async.commit_group;" ::: "memory")
#define CP_WAIT0()  asm volatile("cp.async.wait_group 0;" ::: "memory")
#define CP_WAIT1()  asm volatile("cp.async.wait_group 1;" ::: "memory")

__device__ __forceinline__ void ldsm4(unsigned* r, unsigned addr) {
    asm volatile("ldmatrix.sync.aligned.m8n8.x4.shared.b16 {%0,%1,%2,%3}, [%4];"
                 : "=r"(r[0]), "=r"(r[1]), "=r"(r[2]), "=r"(r[3]) : "r"(addr));
}

__device__ __forceinline__ void mma_bf16(float* c, const unsigned* a, const unsigned* b) {
    asm volatile(
        "mma.sync.aligned.m16n8k16.row.col.f32.bf16.bf16.f32 "
        "{%0,%1,%2,%3}, {%4,%5,%6,%7}, {%8,%9}, {%0,%1,%2,%3};"
        : "+f"(c[0]), "+f"(c[1]), "+f"(c[2]), "+f"(c[3])
        : "r"(a[0]), "r"(a[1]), "r"(a[2]), "r"(a[3]), "r"(b[0]), "r"(b[1]));
}

__device__ __forceinline__ unsigned swz(unsigned off) {
    return off ^ ((off >> 3) & 0x70);
}

// ---------------------------------------------------------------------------
// Split-bf16 tensor-core GEMM:  C[m,n] = sum_k A[m,k]*B[n,k]
// 3 terms: hh + hl + lh. CTA tile 128x128, K chunks of 64 bf16 (SW128),
// 3-stage cp.async pipeline. 8 warps (4M x 2N), warp tile 32x64.
// MODE 0: fp32 C.  MODE 1: split hi/lo bf16 C.
// ---------------------------------------------------------------------------
template <int MODE>
__global__ void __launch_bounds__(256) gemm_mma(
    const __nv_bfloat16* __restrict__ A0, const __nv_bfloat16* __restrict__ A1,
    const __nv_bfloat16* __restrict__ B0, const __nv_bfloat16* __restrict__ B1,
    float* __restrict__ Cf, __nv_bfloat16* __restrict__ Ch,
    __nv_bfloat16* __restrict__ Cl,
    int K, size_t sA, size_t sB, size_t sC, int ldc)
{
    constexpr unsigned TILE = 128 * 64 * 2;   // 16 KB per operand tile
    constexpr unsigned STAGE = 4 * TILE;      // Ah, Al, Bh, Bl = 64 KB

    extern __shared__ char smem[];
    const unsigned sbase = smem_u32(smem);

    const int tid = threadIdx.x;
    const int lid = tid & 31;
    const int wid = tid >> 5;
    const int wm = wid & 3;        // M slab (32 rows)
    const int wn = wid >> 2;       // N slab (64 cols)

    const size_t zb = blockIdx.z;
    const __nv_bfloat16* AP[2] = { A0 + zb * sA, A1 + zb * sA };
    const __nv_bfloat16* BP[2] = { B0 + zb * sB, B1 + zb * sB };
    const size_t rm0 = (size_t)blockIdx.y * 128;
    const size_t rn0 = (size_t)blockIdx.x * 128;
    const int NC = K >> 6;

    float c[2][8][4] = {};

    const int al_r  = lid & 15;
    const int al_k  = (lid >> 4) & 1;
    const int bl_r  = (lid & 7) + ((lid >> 4) << 3);
    const int bl_k  = (lid >> 3) & 1;

    auto load_stage = [&](int st, int ck) {
        const unsigned sdst = sbase + (unsigned)st * STAGE;
        const int k0 = ck << 6;
        #pragma unroll
        for (int t4 = 0; t4 < 4; t4++) {
            const __nv_bfloat16* src = (t4 < 2) ? AP[t4] : BP[t4 - 2];
            const size_t r0 = (t4 < 2) ? rm0 : rn0;
            #pragma unroll
            for (int i = 0; i < 4; i++) {
                int idx = i * 256 + tid;
                int row = idx >> 3, g = idx & 7;
                const __nv_bfloat16* gs = src + (r0 + row) * (size_t)K + k0 + g * 8;
                unsigned d = sdst + (unsigned)t4 * TILE + swz((unsigned)(row * 128 + g * 16));
                CP_ASYNC16(d, gs);
            }
        }
    };

    // 3-stage prologue (all our K have NC >= 8)
    load_stage(0, 0); CP_COMMIT();
    load_stage(1, 1); CP_COMMIT();

    for (int ck = 0; ck < NC; ck++) {
        if (ck + 1 < NC) CP_WAIT1(); else CP_WAIT0();
        __syncthreads();
        if (ck + 2 < NC) {
            load_stage((ck + 2) % 3, ck + 2);
            CP_COMMIT();
        }

        const unsigned sb2 = sbase + (unsigned)(ck % 3) * STAGE;
        #pragma unroll
        for (int ks = 0; ks < 4; ks++) {
            unsigned af[2][2][4];
            unsigned bf[2][8][2];
            #pragma unroll
            for (int sp = 0; sp < 2; sp++) {
                #pragma unroll
                for (int mt = 0; mt < 2; mt++) {
                    unsigned addr = sb2 + (unsigned)sp * TILE +
                        swz((unsigned)((wm * 32 + mt * 16 + al_r) * 128 + ks * 32 + al_k * 16));
                    ldsm4(af[sp][mt], addr);
                }
                #pragma unroll
                for (int np = 0; np < 4; np++) {
                    unsigned r[4];
                    unsigned addr = sb2 + (unsigned)(2 + sp) * TILE +
                        swz((unsigned)((wn * 64 + np * 16 + bl_r) * 128 + ks * 32 + bl_k * 16));
                    ldsm4(r, addr);
                    bf[sp][2 * np][0] = r[0]; bf[sp][2 * np][1] = r[1];
                    bf[sp][2 * np + 1][0] = r[2]; bf[sp][2 * np + 1][1] = r[3];
                }
            }
            // 3 terms: hh, hl, lh
            #pragma unroll
            for (int tm = 0; tm < 3; tm++) {
                const int i = (tm == 2) ? 1 : 0;
                const int j = (tm == 1) ? 1 : 0;
                #pragma unroll
                for (int mt = 0; mt < 2; mt++)
                    #pragma unroll
                    for (int nt = 0; nt < 8; nt++)
                        mma_bf16(c[mt][nt], af[i][mt], bf[j][nt]);
            }
        }
    }
    __syncthreads();

    const int qr = lid >> 2;
    const int qc = (lid & 3) * 2;
    #pragma unroll
    for (int mt = 0; mt < 2; mt++) {
        #pragma unroll
        for (int nt = 0; nt < 8; nt++) {
            size_t gr = rm0 + wm * 32 + mt * 16 + qr;
            int gc = (int)rn0 + wn * 64 + nt * 8 + qc;
            if (MODE == 1) {
                #pragma unroll
                for (int half = 0; half < 2; half++) {
                    float v0 = c[mt][nt][2 * half + 0];
                    float v1 = c[mt][nt][2 * half + 1];
                    size_t o = zb * sC + (gr + half * 8) * (size_t)ldc + gc;
                    __nv_bfloat162 hv, lv;
                    hv.x = __float2bfloat16(v0);
                    hv.y = __float2bfloat16(v1);
                    lv.x = __float2bfloat16(v0 - __bfloat162float(hv.x));
                    lv.y = __float2bfloat16(v1 - __bfloat162float(hv.y));
                    *reinterpret_cast<__nv_bfloat162*>(Ch + o) = hv;
                    *reinterpret_cast<__nv_bfloat162*>(Cl + o) = lv;
                }
            } else {
                #pragma unroll
                for (int half = 0; half < 2; half++) {
                    size_t o = zb * sC + (gr + half * 8) * (size_t)ldc + gc;
                    float2 v = make_float2(c[mt][nt][2 * half], c[mt][nt][2 * half + 1]);
                    *reinterpret_cast<float2*>(Cf + o) = v;
                }
            }
        }
    }
}

// ---------------------------------------------------------------------------
// fp32 -> 2-way bf16 split (elementwise, vectorized) — for weights
// ---------------------------------------------------------------------------
__global__ void __launch_bounds__(256) split2_k(
    const float4* __restrict__ x, __nv_bfloat16* __restrict__ h,
    __nv_bfloat16* __restrict__ l, int n4)
{
    for (int i = blockIdx.x * blockDim.x + threadIdx.x; i < n4;
         i += gridDim.x * blockDim.x) {
        float4 v = x[i];
        float a[4] = {v.x, v.y, v.z, v.w};
        __nv_bfloat16 hh[4], ll[4];
        #pragma unroll
        for (int k = 0; k < 4; k++) {
            hh[k] = __float2bfloat16(a[k]);
            ll[k] = __float2bfloat16(a[k] - __bfloat162float(hh[k]));
        }
        __nv_bfloat162 p0, p1;
        p0.x = hh[0]; p0.y = hh[1]; p1.x = hh[2]; p1.y = hh[3];
        reinterpret_cast<__nv_bfloat162*>(h)[2 * i] = p0;
        reinterpret_cast<__nv_bfloat162*>(h)[2 * i + 1] = p1;
        p0.x = ll[0]; p0.y = ll[1]; p1.x = ll[2]; p1.y = ll[3];
        reinterpret_cast<__nv_bfloat162*>(l)[2 * i] = p0;
        reinterpret_cast<__nv_bfloat162*>(l)[2 * i + 1] = p1;
    }
}

// ---------------------------------------------------------------------------
// region prep: one CTA per (b,r) row. Writes rf_h/rf_l; computes rd0 = row.Ws0.
// ---------------------------------------------------------------------------
__global__ void __launch_bounds__(256) region_prep_k(
    const float* __restrict__ region, const float* __restrict__ Ws0,
    __nv_bfloat16* __restrict__ rf_h, __nv_bfloat16* __restrict__ rf_l,
    float* __restrict__ rd0)
{
    size_t row = blockIdx.x;
    int t = threadIdx.x;
    float4 a = *reinterpret_cast<const float4*>(region + row * DD + t * 4);
    float4 w = *reinterpret_cast<const float4*>(Ws0 + t * 4);

    __nv_bfloat162 h0, h1, l0, l1;
    h0.x = __float2bfloat16(a.x); h0.y = __float2bfloat16(a.y);
    h1.x = __float2bfloat16(a.z); h1.y = __float2bfloat16(a.w);
    l0.x = __float2bfloat16(a.x - __bfloat162float(h0.x));
    l0.y = __float2bfloat16(a.y - __bfloat162float(h0.y));
    l1.x = __float2bfloat16(a.z - __bfloat162float(h1.x));
    l1.y = __float2bfloat16(a.w - __bfloat162float(h1.y));
    reinterpret_cast<__nv_bfloat162*>(rf_h + row * DD)[2 * t] = h0;
    reinterpret_cast<__nv_bfloat162*>(rf_h + row * DD)[2 * t + 1] = h1;
    reinterpret_cast<__nv_bfloat162*>(rf_l + row * DD)[2 * t] = l0;
    reinterpret_cast<__nv_bfloat162*>(rf_l + row * DD)[2 * t + 1] = l1;

    float p = a.x * w.x + a.y * w.y + a.z * w.z + a.w * w.w;
    __shared__ float red[8];
    #pragma unroll
    for (int o = 16; o; o >>= 1) p += __shfl_xor_sync(0xffffffffu, p, o);
    if ((t & 31) == 0) red[t >> 5] = p;
    __syncthreads();
    if (t == 0) {
        float s = 0.f;
        #pragma unroll
        for (int i = 0; i < 8; i++) s += red[i];
        rd0[row] = s;
    }
}

// ---------------------------------------------------------------------------
// query prep: one CTA per (b,t) row. Writes qe_h/l and qe2_h/l (= qe*Ws2);
// computes qv = row.v and y1 = row.Ws1.
// ---------------------------------------------------------------------------
__global__ void __launch_bounds__(256) query_prep_k(
    const float* __restrict__ query, const float* __restrict__ v,
    const float* __restrict__ Ws1, const float* __restrict__ Ws2,
    __nv_bfloat16* __restrict__ qe_h, __nv_bfloat16* __restrict__ qe_l,
    __nv_bfloat16* __restrict__ qe2_h, __nv_bfloat16* __restrict__ qe2_l,
    float* __restrict__ qv, float* __restrict__ y1)
{
    size_t row = blockIdx.x;
    int t = threadIdx.x;
    float4 a = *reinterpret_cast<const float4*>(query + row * DD + t * 4);
    float4 vv = *reinterpret_cast<const float4*>(v + t * 4);
    float4 w1 = *reinterpret_cast<const float4*>(Ws1 + t * 4);
    float4 w2 = *reinterpret_cast<const float4*>(Ws2 + t * 4);

    __nv_bfloat162 h0, h1, l0, l1;
    h0.x = __float2bfloat16(a.x); h0.y = __float2bfloat16(a.y);
    h1.x = __float2bfloat16(a.z); h1.y = __float2bfloat16(a.w);
    l0.x = __float2bfloat16(a.x - __bfloat162float(h0.x));
    l0.y = __float2bfloat16(a.y - __bfloat162float(h0.y));
    l1.x = __float2bfloat16(a.z - __bfloat162float(h1.x));
    l1.y = __float2bfloat16(a.w - __bfloat162float(h1.y));
    reinterpret_cast<__nv_bfloat162*>(qe_h + row * DD)[2 * t] = h0;
    reinterpret_cast<__nv_bfloat162*>(qe_h + row * DD)[2 * t + 1] = h1;
    reinterpret_cast<__nv_bfloat162*>(qe_l + row * DD)[2 * t] = l0;
    reinterpret_cast<__nv_bfloat162*>(qe_l + row * DD)[2 * t + 1] = l1;

    float b0 = a.x * w2.x, b1 = a.y * w2.y, b2 = a.z * w2.z, b3 = a.w * w2.w;
    h0.x = __float2bfloat16(b0); h0.y = __float2bfloat16(b1);
    h1.x = __float2bfloat16(b2); h1.y = __float2bfloat16(b3);
    l0.x = __float2bfloat16(b0 - __bfloat162float(h0.x));
    l0.y = __float2bfloat16(b1 - __bfloat162float(h0.y));
    l1.x = __float2bfloat16(b2 - __bfloat162float(h1.x));
    l1.y = __float2bfloat16(b3 - __bfloat162float(h1.y));
    reinterpret_cast<__nv_bfloat162*>(qe2_h + row * DD)[2 * t] = h0;
    reinterpret_cast<__nv_bfloat162*>(qe2_h + row * DD)[2 * t + 1] = h1;
    reinterpret_cast<__nv_bfloat162*>(qe2_l + row * DD)[2 * t] = l0;
    reinterpret_cast<__nv_bfloat162*>(qe2_l + row * DD)[2 * t + 1] = l1;

    float p = a.x * vv.x + a.y * vv.y + a.z * vv.z + a.w * vv.w;
    float q = a.x * w1.x + a.y * w1.y + a.z * w1.z + a.w * w1.w;
    __shared__ float red[16];
    #pragma unroll
    for (int o = 16; o; o >>= 1) {
        p += __shfl_xor_sync(0xffffffffu, p, o);
        q += __shfl_xor_sync(0xffffffffu, q, o);
    }
    if ((t & 31) == 0) { red[t >> 5] = p; red[8 + (t >> 5)] = q; }
    __syncthreads();
    if (t == 0) {
        float s = 0.f, s2 = 0.f;
        #pragma unroll
        for (int i = 0; i < 8; i++) { s += red[i]; s2 += red[8 + i]; }
        qv[row] = s;
        y1[row] = s2;
    }
}

// ---------------------------------------------------------------------------
// v[d] = sum_h Wq[d,h] * br[h]
// ---------------------------------------------------------------------------
__global__ void __launch_bounds__(256) matvec_k(
    const float* __restrict__ W, const float* __restrict__ b,
    float* __restrict__ v, int H)
{
    const float* row = W + (size_t)blockIdx.x * H;
    int t = threadIdx.x;
    float p = 0.f;
    for (int h = t * 4; h < H; h += 1024) {
        float4 wv = *reinterpret_cast<const float4*>(row + h);
        float4 bv = *reinterpret_cast<const float4*>(b + h);
        p = fmaf(wv.x, bv.x, p); p = fmaf(wv.y, bv.y, p);
        p = fmaf(wv.z, bv.z, p); p = fmaf(wv.w, bv.w, p);
    }
    __shared__ float red[8];
    #pragma unroll
    for (int o = 16; o; o >>= 1) p += __shfl_xor_sync(0xffffffffu, p, o);
    if ((t & 31) == 0) red[t >> 5] = p;
    __syncthreads();
    if (t == 0) {
        float s = 0.f;
        #pragma unroll
        for (int i = 0; i < 8; i++) s += red[i];
        v[blockIdx.x] = s;
    }
}

// ---------------------------------------------------------------------------
// Fused softmax + weighted reduction:
// out[b,r] = rd0[b,r] + sum_t softmax(scores[b,r,:]+qv[b,:])[t] * (y1[b,t]+G[b,r,t]) + bs
// ---------------------------------------------------------------------------
__global__ void __launch_bounds__(256) softmax_out(
    const float* __restrict__ S, const float* __restrict__ G,
    const float* __restrict__ qv, const float* __restrict__ y1,
    const float* __restrict__ rd0, const float* __restrict__ bs,
    float* __restrict__ out)
{
    size_t rowi = blockIdx.x;
    const float* row = S + rowi * TT;
    const float* grow = G + rowi * TT;
    size_t boff = (rowi / RR) * TT;
    int t = threadIdx.x;
    float v0 = row[t] + qv[boff + t];
    float v1 = row[t + 256] + qv[boff + t + 256];

    __shared__ float red[16];

    float m = fmaxf(v0, v1);
    #pragma unroll
    for (int o = 16; o; o >>= 1) m = fmaxf(m, __shfl_xor_sync(0xffffffffu, m, o));
    if ((t & 31) == 0) red[t >> 5] = m;
    __syncthreads();
    if (t == 0) {
        float x = red[0];
        #pragma unroll
        for (int i = 1; i < 8; i++) x = fmaxf(x, red[i]);
        red[0] = x;
    }
    __syncthreads();
    m = red[0];
    __syncthreads();

    float e0 = expf(v0 - m);
    float e1 = expf(v1 - m);
    float den = e0 + e1;
    float num = e0 * (y1[boff + t] + grow[t]) +
                e1 * (y1[boff + t + 256] + grow[t + 256]);
    #pragma unroll
    for (int o = 16; o; o >>= 1) {
        den += __shfl_xor_sync(0xffffffffu, den, o);
        num += __shfl_xor_sync(0xffffffffu, num, o);
    }
    if ((t & 31) == 0) { red[t >> 5] = den; red[8 + (t >> 5)] = num; }
    __syncthreads();
    if (t == 0) {
        float sd = 0.f, sn = 0.f;
        #pragma unroll
        for (int i = 0; i < 8; i++) { sd += red[i]; sn += red[8 + i]; }
        out[rowi] = rd0[rowi] + sn / sd + bs[0];
    }
}

// ---------------------------------------------------------------------------
extern "C" void kernel_launch(void* const* d_in, const int* in_sizes, int n_in,
                              void* d_out, int out_size)
{
    const float* region = (const float*)d_in[0];
    const float* query  = (const float*)d_in[1];
    const float* Wr     = (const float*)d_in[2];
    const float* br     = (const float*)d_in[3];
    const float* Wq     = (const float*)d_in[4];
    const float* bq     = (const float*)d_in[5];
    const float* Ws     = (const float*)d_in[6];
    const float* bs     = (const float*)d_in[7];
    float* out = (float*)d_out;
    (void)bq;  // softmax-invariant terms drop out

    __nv_bfloat16 *Wr_h, *Wr_l, *Wq_h, *Wq_l, *M2_h, *M2_l;
    __nv_bfloat16 *rf_h, *rf_l, *qe_h, *qe_l, *qe2_h, *qe2_l, *Nt_h, *Nt_l;
    float *scores, *G, *v, *qv, *y1, *rd0;
    cudaGetSymbolAddress((void**)&Wr_h, g_Wr_h);
    cudaGetSymbolAddress((void**)&Wr_l, g_Wr_l);
    cudaGetSymbolAddress((void**)&Wq_h, g_Wq_h);
    cudaGetSymbolAddress((void**)&Wq_l, g_Wq_l);
    cudaGetSymbolAddress((void**)&M2_h, g_M2_h);
    cudaGetSymbolAddress((void**)&M2_l, g_M2_l);
    cudaGetSymbolAddress((void**)&rf_h, g_rf_h);
    cudaGetSymbolAddress((void**)&rf_l, g_rf_l);
    cudaGetSymbolAddress((void**)&qe_h, g_qe_h);
    cudaGetSymbolAddress((void**)&qe_l, g_qe_l);
    cudaGetSymbolAddress((void**)&qe2_h, g_qe2_h);
    cudaGetSymbolAddress((void**)&qe2_l, g_qe2_l);
    cudaGetSymbolAddress((void**)&Nt_h, g_Nt_h);
    cudaGetSymbolAddress((void**)&Nt_l, g_Nt_l);
    cudaGetSymbolAddress((void**)&scores, g_scores);
    cudaGetSymbolAddress((void**)&G, g_G);
    cudaGetSymbolAddress((void**)&v, g_v);
    cudaGetSymbolAddress((void**)&qv, g_qv);
    cudaGetSymbolAddress((void**)&y1, g_y1);
    cudaGetSymbolAddress((void**)&rd0, g_rd0);

    const int SMEM = 3 * 4 * 16384;   // 196608 (3-stage)
    cudaFuncSetAttribute(gemm_mma<0>, cudaFuncAttributeMaxDynamicSharedMemorySize, SMEM);
    cudaFuncSetAttribute(gemm_mma<1>, cudaFuncAttributeMaxDynamicSharedMemorySize, SMEM);

    // 1) weight splits + bias matvec
    split2_k<<<512, 256>>>((const float4*)Wr, Wr_h, Wr_l, DD * HH / 4);
    split2_k<<<512, 256>>>((const float4*)Wq, Wq_h, Wq_l, DD * HH / 4);
    matvec_k<<<DD, 256>>>(Wq, br, v, HH);
    // 2) fused activation prep (single pass over region and query)
    region_prep_k<<<BB * RR, 256>>>(region, Ws, rf_h, rf_l, rd0);
    query_prep_k<<<BB * TT, 256>>>(query, v, Ws + DD, Ws + 2 * DD,
                                   qe_h, qe_l, qe2_h, qe2_l, qv, y1);
    // 3) M2[d,e] = sum_h Wr[d,h] Wq[e,h]  (e contiguous), split output
    gemm_mma<1><<<dim3(DD / 128, DD / 128, 1), 256, SMEM>>>(
        Wr_h, Wr_l, Wq_h, Wq_l, nullptr, M2_h, M2_l, HH, 0, 0, 0, DD);
    // 4) Nt[b][t,d] = sum_e qe[b,t,e] M2[d,e]  (d contiguous), split output
    gemm_mma<1><<<dim3(DD / 128, TT / 128, BB), 256, SMEM>>>(
        qe_h, qe_l, M2_h, M2_l, nullptr, Nt_h, Nt_l,
        DD, (size_t)TT * DD, 0, (size_t)TT * DD, DD);
    // 5) scores[b][r,t] = sum_d rf[b,r,d] Nt[b][t,d]  (batched NT)
    gemm_mma<0><<<dim3(TT / 128, RR / 128, BB), 256, SMEM>>>(
        rf_h, rf_l, Nt_h, Nt_l, scores, nullptr, nullptr,
        DD, (size_t)RR * DD, (size_t)TT * DD, (size_t)RR * TT, TT);
    // 6) G[b][r,t] = sum_d rf[b,r,d] qe2[b,t,d]  (batched NT, A shared with scores)
    gemm_mma<0><<<dim3(TT / 128, RR / 128, BB), 256, SMEM>>>(
        rf_h, rf_l, qe2_h, qe2_l, G, nullptr, nullptr,
        DD, (size_t)RR * DD, (size_t)TT * DD, (size_t)RR * TT, TT);
    // 7) fused softmax + weighted sum + final output
    softmax_out<<<BB * RR, 256>>>(scores, G, qv, y1, rd0, bs, out);
}

// round 9
// speedup vs baseline: 1.1189x; 1.0277x over previous
#include <cuda_runtime.h>
#include <cuda_bf16.h>

#define BB 16
#define RR 1024
#define TT 512
#define DD 1024
#define HH 1024

// ---------------------------------------------------------------------------
// Scratch (device globals — allocations are forbidden)
// ---------------------------------------------------------------------------
__device__ __nv_bfloat16 g_Wr_h[DD * HH], g_Wr_l[DD * HH];
__device__ __nv_bfloat16 g_Wq_h[DD * HH], g_Wq_l[DD * HH];
__device__ __nv_bfloat16 g_M2_h[DD * DD], g_M2_l[DD * DD];       // M2[d,e] = sum_h Wr[d,h]Wq[e,h]
__device__ __nv_bfloat16 g_rf_h[(size_t)BB * RR * DD], g_rf_l[(size_t)BB * RR * DD];
__device__ __nv_bfloat16 g_qe_h[(size_t)BB * TT * DD], g_qe_l[(size_t)BB * TT * DD];
__device__ __nv_bfloat16 g_qe2_h[(size_t)BB * TT * DD], g_qe2_l[(size_t)BB * TT * DD]; // qe*Ws2
__device__ __nv_bfloat16 g_Nt_h[(size_t)BB * TT * DD], g_Nt_l[(size_t)BB * TT * DD];   // Nt[b][t,d]
__device__ float         g_scores[(size_t)BB * RR * TT];
__device__ float         g_G[(size_t)BB * RR * TT];
__device__ float         g_v[DD];
__device__ float         g_qv[BB * TT];
__device__ float         g_y1[BB * TT];
__device__ float         g_rd0[BB * RR];

// ---------------------------------------------------------------------------
// PTX helpers (sm_80-level features only: ldmatrix, cp.async, mma.sync)
// ---------------------------------------------------------------------------
__device__ __forceinline__ unsigned smem_u32(const void* p) {
    unsigned a;
    asm("{ .reg .u64 t; cvta.to.shared.u64 t, %1; cvt.u32.u64 %0, t; }" : "=r"(a) : "l"(p));
    return a;
}

#define CP_ASYNC16(dst, src) \
    asm volatile("cp.async.cg.shared.global [%0], [%1], 16;" :: "r"(dst), "l"(src))
#define CP_COMMIT() asm volatile("cp.async.commit_group;" ::: "memory")
#define CP_WAIT0()  asm volatile("cp.async.wait_group 0;" ::: "memory")
#define CP_WAIT1()  asm volatile("cp.async.wait_group 1;" ::: "memory")

__device__ __forceinline__ void ldsm4(unsigned* r, unsigned addr) {
    asm volatile("ldmatrix.sync.aligned.m8n8.x4.shared.b16 {%0,%1,%2,%3}, [%4];"
                 : "=r"(r[0]), "=r"(r[1]), "=r"(r[2]), "=r"(r[3]) : "r"(addr));
}

__device__ __forceinline__ void mma_bf16(float* c, const unsigned* a, const unsigned* b) {
    asm volatile(
        "mma.sync.aligned.m16n8k16.row.col.f32.bf16.bf16.f32 "
        "{%0,%1,%2,%3}, {%4,%5,%6,%7}, {%8,%9}, {%0,%1,%2,%3};"
        : "+f"(c[0]), "+f"(c[1]), "+f"(c[2]), "+f"(c[3])
        : "r"(a[0]), "r"(a[1]), "r"(a[2]), "r"(a[3]), "r"(b[0]), "r"(b[1]));
}

__device__ __forceinline__ unsigned swz(unsigned off) {
    return off ^ ((off >> 3) & 0x70);
}

// ---------------------------------------------------------------------------
// Split-bf16 tensor-core GEMM:  C[m,n] = sum_k A[m,k]*B[n,k]
// 3 terms: hh + hl + lh. CTA tile 128x128, K chunks of 64 bf16 (SW128),
// 3-stage cp.async pipeline. 8 warps (4M x 2N), warp tile 32x64.
// MODE 1: split hi/lo bf16 C.  (used for M2 and Nt)
// ---------------------------------------------------------------------------
__global__ void __launch_bounds__(256) gemm_mma1(
    const __nv_bfloat16* __restrict__ A0, const __nv_bfloat16* __restrict__ A1,
    const __nv_bfloat16* __restrict__ B0, const __nv_bfloat16* __restrict__ B1,
    __nv_bfloat16* __restrict__ Ch, __nv_bfloat16* __restrict__ Cl,
    int K, size_t sA, size_t sB, size_t sC, int ldc)
{
    constexpr unsigned TILE = 128 * 64 * 2;   // 16 KB per operand tile
    constexpr unsigned STAGE = 4 * TILE;      // Ah, Al, Bh, Bl = 64 KB

    extern __shared__ char smem[];
    const unsigned sbase = smem_u32(smem);

    const int tid = threadIdx.x;
    const int lid = tid & 31;
    const int wid = tid >> 5;
    const int wm = wid & 3;
    const int wn = wid >> 2;

    const size_t zb = blockIdx.z;
    const __nv_bfloat16* AP[2] = { A0 + zb * sA, A1 + zb * sA };
    const __nv_bfloat16* BP[2] = { B0 + zb * sB, B1 + zb * sB };
    const size_t rm0 = (size_t)blockIdx.y * 128;
    const size_t rn0 = (size_t)blockIdx.x * 128;
    const int NC = K >> 6;

    float c[2][8][4] = {};

    const int al_r  = lid & 15;
    const int al_k  = (lid >> 4) & 1;
    const int bl_r  = (lid & 7) + ((lid >> 4) << 3);
    const int bl_k  = (lid >> 3) & 1;

    auto load_stage = [&](int st, int ck) {
        const unsigned sdst = sbase + (unsigned)st * STAGE;
        const int k0 = ck << 6;
        #pragma unroll
        for (int t4 = 0; t4 < 4; t4++) {
            const __nv_bfloat16* src = (t4 < 2) ? AP[t4] : BP[t4 - 2];
            const size_t r0 = (t4 < 2) ? rm0 : rn0;
            #pragma unroll
            for (int i = 0; i < 4; i++) {
                int idx = i * 256 + tid;
                int row = idx >> 3, g = idx & 7;
                const __nv_bfloat16* gs = src + (r0 + row) * (size_t)K + k0 + g * 8;
                unsigned d = sdst + (unsigned)t4 * TILE + swz((unsigned)(row * 128 + g * 16));
                CP_ASYNC16(d, gs);
            }
        }
    };

    load_stage(0, 0); CP_COMMIT();
    load_stage(1, 1); CP_COMMIT();

    for (int ck = 0; ck < NC; ck++) {
        if (ck + 1 < NC) CP_WAIT1(); else CP_WAIT0();
        __syncthreads();
        if (ck + 2 < NC) {
            load_stage((ck + 2) % 3, ck + 2);
            CP_COMMIT();
        }

        const unsigned sb2 = sbase + (unsigned)(ck % 3) * STAGE;
        #pragma unroll
        for (int ks = 0; ks < 4; ks++) {
            unsigned af[2][2][4];
            unsigned bf[2][8][2];
            #pragma unroll
            for (int sp = 0; sp < 2; sp++) {
                #pragma unroll
                for (int mt = 0; mt < 2; mt++) {
                    unsigned addr = sb2 + (unsigned)sp * TILE +
                        swz((unsigned)((wm * 32 + mt * 16 + al_r) * 128 + ks * 32 + al_k * 16));
                    ldsm4(af[sp][mt], addr);
                }
                #pragma unroll
                for (int np = 0; np < 4; np++) {
                    unsigned r[4];
                    unsigned addr = sb2 + (unsigned)(2 + sp) * TILE +
                        swz((unsigned)((wn * 64 + np * 16 + bl_r) * 128 + ks * 32 + bl_k * 16));
                    ldsm4(r, addr);
                    bf[sp][2 * np][0] = r[0]; bf[sp][2 * np][1] = r[1];
                    bf[sp][2 * np + 1][0] = r[2]; bf[sp][2 * np + 1][1] = r[3];
                }
            }
            #pragma unroll
            for (int tm = 0; tm < 3; tm++) {
                const int i = (tm == 2) ? 1 : 0;
                const int j = (tm == 1) ? 1 : 0;
                #pragma unroll
                for (int mt = 0; mt < 2; mt++)
                    #pragma unroll
                    for (int nt = 0; nt < 8; nt++)
                        mma_bf16(c[mt][nt], af[i][mt], bf[j][nt]);
            }
        }
    }
    __syncthreads();

    const int qr = lid >> 2;
    const int qc = (lid & 3) * 2;
    #pragma unroll
    for (int mt = 0; mt < 2; mt++) {
        #pragma unroll
        for (int nt = 0; nt < 8; nt++) {
            size_t gr = rm0 + wm * 32 + mt * 16 + qr;
            int gc = (int)rn0 + wn * 64 + nt * 8 + qc;
            #pragma unroll
            for (int half = 0; half < 2; half++) {
                float v0 = c[mt][nt][2 * half + 0];
                float v1 = c[mt][nt][2 * half + 1];
                size_t o = zb * sC + (gr + half * 8) * (size_t)ldc + gc;
                __nv_bfloat162 hv, lv;
                hv.x = __float2bfloat16(v0);
                hv.y = __float2bfloat16(v1);
                lv.x = __float2bfloat16(v0 - __bfloat162float(hv.x));
                lv.y = __float2bfloat16(v1 - __bfloat162float(hv.y));
                *reinterpret_cast<__nv_bfloat162*>(Ch + o) = hv;
                *reinterpret_cast<__nv_bfloat162*>(Cl + o) = lv;
            }
        }
    }
}

// ---------------------------------------------------------------------------
// Dual-B GEMM: shared A (rf), two B operands (Nt, qe2), two fp32 outputs
// (scores, G). CTA tile 128x128, 2-stage pipeline (96 KB/stage).
// ---------------------------------------------------------------------------
__global__ void __launch_bounds__(256) gemm_dual(
    const __nv_bfloat16* __restrict__ A0, const __nv_bfloat16* __restrict__ A1,
    const __nv_bfloat16* __restrict__ B0, const __nv_bfloat16* __restrict__ B1,
    const __nv_bfloat16* __restrict__ C0, const __nv_bfloat16* __restrict__ C1,
    float* __restrict__ S, float* __restrict__ G,
    int K, size_t sA, size_t sB, size_t sC, int ldc)
{
    constexpr unsigned TILE = 128 * 64 * 2;   // 16 KB
    constexpr unsigned STAGE = 6 * TILE;      // Ah, Al, Nh, Nl, Qh, Ql = 96 KB

    extern __shared__ char smem[];
    const unsigned sbase = smem_u32(smem);

    const int tid = threadIdx.x;
    const int lid = tid & 31;
    const int wid = tid >> 5;
    const int wm = wid & 3;
    const int wn = wid >> 2;

    const size_t zb = blockIdx.z;
    const __nv_bfloat16* P[6] = { A0 + zb * sA, A1 + zb * sA,
                                  B0 + zb * sB, B1 + zb * sB,
                                  C0 + zb * sB, C1 + zb * sB };
    const size_t rm0 = (size_t)blockIdx.y * 128;
    const size_t rn0 = (size_t)blockIdx.x * 128;
    const int NC = K >> 6;

    float c1[2][8][4] = {};
    float c2[2][8][4] = {};

    const int al_r  = lid & 15;
    const int al_k  = (lid >> 4) & 1;
    const int bl_r  = (lid & 7) + ((lid >> 4) << 3);
    const int bl_k  = (lid >> 3) & 1;

    auto load_stage = [&](int st, int ck) {
        const unsigned sdst = sbase + (unsigned)st * STAGE;
        const int k0 = ck << 6;
        #pragma unroll
        for (int t6 = 0; t6 < 6; t6++) {
            const __nv_bfloat16* src = P[t6];
            const size_t r0 = (t6 < 2) ? rm0 : rn0;
            #pragma unroll
            for (int i = 0; i < 4; i++) {
                int idx = i * 256 + tid;
                int row = idx >> 3, g = idx & 7;
                const __nv_bfloat16* gs = src + (r0 + row) * (size_t)K + k0 + g * 8;
                unsigned d = sdst + (unsigned)t6 * TILE + swz((unsigned)(row * 128 + g * 16));
                CP_ASYNC16(d, gs);
            }
        }
    };

    load_stage(0, 0); CP_COMMIT();

    for (int ck = 0; ck < NC; ck++) {
        if (ck + 1 < NC) {
            load_stage((ck + 1) & 1, ck + 1);
            CP_COMMIT();
            CP_WAIT1();
        } else {
            CP_WAIT0();
        }
        __syncthreads();

        const unsigned sb2 = sbase + (unsigned)(ck & 1) * STAGE;
        #pragma unroll
        for (int ks = 0; ks < 4; ks++) {
            unsigned af[2][2][4];
            #pragma unroll
            for (int sp = 0; sp < 2; sp++)
                #pragma unroll
                for (int mt = 0; mt < 2; mt++) {
                    unsigned addr = sb2 + (unsigned)sp * TILE +
                        swz((unsigned)((wm * 32 + mt * 16 + al_r) * 128 + ks * 32 + al_k * 16));
                    ldsm4(af[sp][mt], addr);
                }
            // ---- product 1: B = Nt (tiles 2,3) -> c1
            {
                unsigned bf[2][8][2];
                #pragma unroll
                for (int sp = 0; sp < 2; sp++)
                    #pragma unroll
                    for (int np = 0; np < 4; np++) {
                        unsigned r[4];
                        unsigned addr = sb2 + (unsigned)(2 + sp) * TILE +
                            swz((unsigned)((wn * 64 + np * 16 + bl_r) * 128 + ks * 32 + bl_k * 16));
                        ldsm4(r, addr);
                        bf[sp][2 * np][0] = r[0]; bf[sp][2 * np][1] = r[1];
                        bf[sp][2 * np + 1][0] = r[2]; bf[sp][2 * np + 1][1] = r[3];
                    }
                #pragma unroll
                for (int tm = 0; tm < 3; tm++) {
                    const int i = (tm == 2) ? 1 : 0;
                    const int j = (tm == 1) ? 1 : 0;
                    #pragma unroll
                    for (int mt = 0; mt < 2; mt++)
                        #pragma unroll
                        for (int nt = 0; nt < 8; nt++)
                            mma_bf16(c1[mt][nt], af[i][mt], bf[j][nt]);
                }
            }
            // ---- product 2: B = qe2 (tiles 4,5) -> c2
            {
                unsigned bf[2][8][2];
                #pragma unroll
                for (int sp = 0; sp < 2; sp++)
                    #pragma unroll
                    for (int np = 0; np < 4; np++) {
                        unsigned r[4];
                        unsigned addr = sb2 + (unsigned)(4 + sp) * TILE +
                            swz((unsigned)((wn * 64 + np * 16 + bl_r) * 128 + ks * 32 + bl_k * 16));
                        ldsm4(r, addr);
                        bf[sp][2 * np][0] = r[0]; bf[sp][2 * np][1] = r[1];
                        bf[sp][2 * np + 1][0] = r[2]; bf[sp][2 * np + 1][1] = r[3];
                    }
                #pragma unroll
                for (int tm = 0; tm < 3; tm++) {
                    const int i = (tm == 2) ? 1 : 0;
                    const int j = (tm == 1) ? 1 : 0;
                    #pragma unroll
                    for (int mt = 0; mt < 2; mt++)
                        #pragma unroll
                        for (int nt = 0; nt < 8; nt++)
                            mma_bf16(c2[mt][nt], af[i][mt], bf[j][nt]);
                }
            }
        }
        __syncthreads();
    }

    const int qr = lid >> 2;
    const int qc = (lid & 3) * 2;
    #pragma unroll
    for (int mt = 0; mt < 2; mt++) {
        #pragma unroll
        for (int nt = 0; nt < 8; nt++) {
            size_t gr = rm0 + wm * 32 + mt * 16 + qr;
            int gc = (int)rn0 + wn * 64 + nt * 8 + qc;
            #pragma unroll
            for (int half = 0; half < 2; half++) {
                size_t o = zb * sC + (gr + half * 8) * (size_t)ldc + gc;
                *reinterpret_cast<float2*>(S + o) =
                    make_float2(c1[mt][nt][2 * half], c1[mt][nt][2 * half + 1]);
                *reinterpret_cast<float2*>(G + o) =
                    make_float2(c2[mt][nt][2 * half], c2[mt][nt][2 * half + 1]);
            }
        }
    }
}

// ---------------------------------------------------------------------------
// fp32 -> 2-way bf16 split (elementwise, vectorized) — for weights
// ---------------------------------------------------------------------------
__global__ void __launch_bounds__(256) split2_k(
    const float4* __restrict__ x, __nv_bfloat16* __restrict__ h,
    __nv_bfloat16* __restrict__ l, int n4)
{
    for (int i = blockIdx.x * blockDim.x + threadIdx.x; i < n4;
         i += gridDim.x * blockDim.x) {
        float4 v = x[i];
        float a[4] = {v.x, v.y, v.z, v.w};
        __nv_bfloat16 hh[4], ll[4];
        #pragma unroll
        for (int k = 0; k < 4; k++) {
            hh[k] = __float2bfloat16(a[k]);
            ll[k] = __float2bfloat16(a[k] - __bfloat162float(hh[k]));
        }
        __nv_bfloat162 p0, p1;
        p0.x = hh[0]; p0.y = hh[1]; p1.x = hh[2]; p1.y = hh[3];
        reinterpret_cast<__nv_bfloat162*>(h)[2 * i] = p0;
        reinterpret_cast<__nv_bfloat162*>(h)[2 * i + 1] = p1;
        p0.x = ll[0]; p0.y = ll[1]; p1.x = ll[2]; p1.y = ll[3];
        reinterpret_cast<__nv_bfloat162*>(l)[2 * i] = p0;
        reinterpret_cast<__nv_bfloat162*>(l)[2 * i + 1] = p1;
    }
}

// ---------------------------------------------------------------------------
// region prep: one CTA per (b,r) row. Writes rf_h/rf_l; computes rd0 = row.Ws0.
// ---------------------------------------------------------------------------
__global__ void __launch_bounds__(256) region_prep_k(
    const float* __restrict__ region, const float* __restrict__ Ws0,
    __nv_bfloat16* __restrict__ rf_h, __nv_bfloat16* __restrict__ rf_l,
    float* __restrict__ rd0)
{
    size_t row = blockIdx.x;
    int t = threadIdx.x;
    float4 a = *reinterpret_cast<const float4*>(region + row * DD + t * 4);
    float4 w = *reinterpret_cast<const float4*>(Ws0 + t * 4);

    __nv_bfloat162 h0, h1, l0, l1;
    h0.x = __float2bfloat16(a.x); h0.y = __float2bfloat16(a.y);
    h1.x = __float2bfloat16(a.z); h1.y = __float2bfloat16(a.w);
    l0.x = __float2bfloat16(a.x - __bfloat162float(h0.x));
    l0.y = __float2bfloat16(a.y - __bfloat162float(h0.y));
    l1.x = __float2bfloat16(a.z - __bfloat162float(h1.x));
    l1.y = __float2bfloat16(a.w - __bfloat162float(h1.y));
    reinterpret_cast<__nv_bfloat162*>(rf_h + row * DD)[2 * t] = h0;
    reinterpret_cast<__nv_bfloat162*>(rf_h + row * DD)[2 * t + 1] = h1;
    reinterpret_cast<__nv_bfloat162*>(rf_l + row * DD)[2 * t] = l0;
    reinterpret_cast<__nv_bfloat162*>(rf_l + row * DD)[2 * t + 1] = l1;

    float p = a.x * w.x + a.y * w.y + a.z * w.z + a.w * w.w;
    __shared__ float red[8];
    #pragma unroll
    for (int o = 16; o; o >>= 1) p += __shfl_xor_sync(0xffffffffu, p, o);
    if ((t & 31) == 0) red[t >> 5] = p;
    __syncthreads();
    if (t == 0) {
        float s = 0.f;
        #pragma unroll
        for (int i = 0; i < 8; i++) s += red[i];
        rd0[row] = s;
    }
}

// ---------------------------------------------------------------------------
// query prep: one CTA per (b,t) row. Writes qe_h/l and qe2_h/l (= qe*Ws2);
// computes qv = row.v and y1 = row.Ws1.
// ---------------------------------------------------------------------------
__global__ void __launch_bounds__(256) query_prep_k(
    const float* __restrict__ query, const float* __restrict__ v,
    const float* __restrict__ Ws1, const float* __restrict__ Ws2,
    __nv_bfloat16* __restrict__ qe_h, __nv_bfloat16* __restrict__ qe_l,
    __nv_bfloat16* __restrict__ qe2_h, __nv_bfloat16* __restrict__ qe2_l,
    float* __restrict__ qv, float* __restrict__ y1)
{
    size_t row = blockIdx.x;
    int t = threadIdx.x;
    float4 a = *reinterpret_cast<const float4*>(query + row * DD + t * 4);
    float4 vv = *reinterpret_cast<const float4*>(v + t * 4);
    float4 w1 = *reinterpret_cast<const float4*>(Ws1 + t * 4);
    float4 w2 = *reinterpret_cast<const float4*>(Ws2 + t * 4);

    __nv_bfloat162 h0, h1, l0, l1;
    h0.x = __float2bfloat16(a.x); h0.y = __float2bfloat16(a.y);
    h1.x = __float2bfloat16(a.z); h1.y = __float2bfloat16(a.w);
    l0.x = __float2bfloat16(a.x - __bfloat162float(h0.x));
    l0.y = __float2bfloat16(a.y - __bfloat162float(h0.y));
    l1.x = __float2bfloat16(a.z - __bfloat162float(h1.x));
    l1.y = __float2bfloat16(a.w - __bfloat162float(h1.y));
    reinterpret_cast<__nv_bfloat162*>(qe_h + row * DD)[2 * t] = h0;
    reinterpret_cast<__nv_bfloat162*>(qe_h + row * DD)[2 * t + 1] = h1;
    reinterpret_cast<__nv_bfloat162*>(qe_l + row * DD)[2 * t] = l0;
    reinterpret_cast<__nv_bfloat162*>(qe_l + row * DD)[2 * t + 1] = l1;

    float b0 = a.x * w2.x, b1 = a.y * w2.y, b2 = a.z * w2.z, b3 = a.w * w2.w;
    h0.x = __float2bfloat16(b0); h0.y = __float2bfloat16(b1);
    h1.x = __float2bfloat16(b2); h1.y = __float2bfloat16(b3);
    l0.x = __float2bfloat16(b0 - __bfloat162float(h0.x));
    l0.y = __float2bfloat16(b1 - __bfloat162float(h0.y));
    l1.x = __float2bfloat16(b2 - __bfloat162float(h1.x));
    l1.y = __float2bfloat16(b3 - __bfloat162float(h1.y));
    reinterpret_cast<__nv_bfloat162*>(qe2_h + row * DD)[2 * t] = h0;
    reinterpret_cast<__nv_bfloat162*>(qe2_h + row * DD)[2 * t + 1] = h1;
    reinterpret_cast<__nv_bfloat162*>(qe2_l + row * DD)[2 * t] = l0;
    reinterpret_cast<__nv_bfloat162*>(qe2_l + row * DD)[2 * t + 1] = l1;

    float p = a.x * vv.x + a.y * vv.y + a.z * vv.z + a.w * vv.w;
    float q = a.x * w1.x + a.y * w1.y + a.z * w1.z + a.w * w1.w;
    __shared__ float red[16];
    #pragma unroll
    for (int o = 16; o; o >>= 1) {
        p += __shfl_xor_sync(0xffffffffu, p, o);
        q += __shfl_xor_sync(0xffffffffu, q, o);
    }
    if ((t & 31) == 0) { red[t >> 5] = p; red[8 + (t >> 5)] = q; }
    __syncthreads();
    if (t == 0) {
        float s = 0.f, s2 = 0.f;
        #pragma unroll
        for (int i = 0; i < 8; i++) { s += red[i]; s2 += red[8 + i]; }
        qv[row] = s;
        y1[row] = s2;
    }
}

// ---------------------------------------------------------------------------
// v[d] = sum_h Wq[d,h] * br[h]
// ---------------------------------------------------------------------------
__global__ void __launch_bounds__(256) matvec_k(
    const float* __restrict__ W, const float* __restrict__ b,
    float* __restrict__ v, int H)
{
    const float* row = W + (size_t)blockIdx.x * H;
    int t = threadIdx.x;
    float p = 0.f;
    for (int h = t * 4; h < H; h += 1024) {
        float4 wv = *reinterpret_cast<const float4*>(row + h);
        float4 bv = *reinterpret_cast<const float4*>(b + h);
        p = fmaf(wv.x, bv.x, p); p = fmaf(wv.y, bv.y, p);
        p = fmaf(wv.z, bv.z, p); p = fmaf(wv.w, bv.w, p);
    }
    __shared__ float red[8];
    #pragma unroll
    for (int o = 16; o; o >>= 1) p += __shfl_xor_sync(0xffffffffu, p, o);
    if ((t & 31) == 0) red[t >> 5] = p;
    __syncthreads();
    if (t == 0) {
        float s = 0.f;
        #pragma unroll
        for (int i = 0; i < 8; i++) s += red[i];
        v[blockIdx.x] = s;
    }
}

// ---------------------------------------------------------------------------
// Fused softmax + weighted reduction:
// out[b,r] = rd0[b,r] + sum_t softmax(scores[b,r,:]+qv[b,:])[t] * (y1[b,t]+G[b,r,t]) + bs
// ---------------------------------------------------------------------------
__global__ void __launch_bounds__(256) softmax_out(
    const float* __restrict__ S, const float* __restrict__ G,
    const float* __restrict__ qv, const float* __restrict__ y1,
    const float* __restrict__ rd0, const float* __restrict__ bs,
    float* __restrict__ out)
{
    size_t rowi = blockIdx.x;
    const float* row = S + rowi * TT;
    const float* grow = G + rowi * TT;
    size_t boff = (rowi / RR) * TT;
    int t = threadIdx.x;
    float v0 = row[t] + qv[boff + t];
    float v1 = row[t + 256] + qv[boff + t + 256];

    __shared__ float red[16];

    float m = fmaxf(v0, v1);
    #pragma unroll
    for (int o = 16; o; o >>= 1) m = fmaxf(m, __shfl_xor_sync(0xffffffffu, m, o));
    if ((t & 31) == 0) red[t >> 5] = m;
    __syncthreads();
    if (t == 0) {
        float x = red[0];
        #pragma unroll
        for (int i = 1; i < 8; i++) x = fmaxf(x, red[i]);
        red[0] = x;
    }
    __syncthreads();
    m = red[0];
    __syncthreads();

    float e0 = expf(v0 - m);
    float e1 = expf(v1 - m);
    float den = e0 + e1;
    float num = e0 * (y1[boff + t] + grow[t]) +
                e1 * (y1[boff + t + 256] + grow[t + 256]);
    #pragma unroll
    for (int o = 16; o; o >>= 1) {
        den += __shfl_xor_sync(0xffffffffu, den, o);
        num += __shfl_xor_sync(0xffffffffu, num, o);
    }
    if ((t & 31) == 0) { red[t >> 5] = den; red[8 + (t >> 5)] = num; }
    __syncthreads();
    if (t == 0) {
        float sd = 0.f, sn = 0.f;
        #pragma unroll
        for (int i = 0; i < 8; i++) { sd += red[i]; sn += red[8 + i]; }
        out[rowi] = rd0[rowi] + sn / sd + bs[0];
    }
}

// ---------------------------------------------------------------------------
extern "C" void kernel_launch(void* const* d_in, const int* in_sizes, int n_in,
                              void* d_out, int out_size)
{
    const float* region = (const float*)d_in[0];
    const float* query  = (const float*)d_in[1];
    const float* Wr     = (const float*)d_in[2];
    const float* br     = (const float*)d_in[3];
    const float* Wq     = (const float*)d_in[4];
    const float* bq     = (const float*)d_in[5];
    const float* Ws     = (const float*)d_in[6];
    const float* bs     = (const float*)d_in[7];
    float* out = (float*)d_out;
    (void)bq;  // softmax-invariant terms drop out

    __nv_bfloat16 *Wr_h, *Wr_l, *Wq_h, *Wq_l, *M2_h, *M2_l;
    __nv_bfloat16 *rf_h, *rf_l, *qe_h, *qe_l, *qe2_h, *qe2_l, *Nt_h, *Nt_l;
    float *scores, *G, *v, *qv, *y1, *rd0;
    cudaGetSymbolAddress((void**)&Wr_h, g_Wr_h);
    cudaGetSymbolAddress((void**)&Wr_l, g_Wr_l);
    cudaGetSymbolAddress((void**)&Wq_h, g_Wq_h);
    cudaGetSymbolAddress((void**)&Wq_l, g_Wq_l);
    cudaGetSymbolAddress((void**)&M2_h, g_M2_h);
    cudaGetSymbolAddress((void**)&M2_l, g_M2_l);
    cudaGetSymbolAddress((void**)&rf_h, g_rf_h);
    cudaGetSymbolAddress((void**)&rf_l, g_rf_l);
    cudaGetSymbolAddress((void**)&qe_h, g_qe_h);
    cudaGetSymbolAddress((void**)&qe_l, g_qe_l);
    cudaGetSymbolAddress((void**)&qe2_h, g_qe2_h);
    cudaGetSymbolAddress((void**)&qe2_l, g_qe2_l);
    cudaGetSymbolAddress((void**)&Nt_h, g_Nt_h);
    cudaGetSymbolAddress((void**)&Nt_l, g_Nt_l);
    cudaGetSymbolAddress((void**)&scores, g_scores);
    cudaGetSymbolAddress((void**)&G, g_G);
    cudaGetSymbolAddress((void**)&v, g_v);
    cudaGetSymbolAddress((void**)&qv, g_qv);
    cudaGetSymbolAddress((void**)&y1, g_y1);
    cudaGetSymbolAddress((void**)&rd0, g_rd0);

    const int SMEM1 = 3 * 4 * 16384;   // 196608 (3-stage, 4 tiles)
    const int SMEMD = 2 * 6 * 16384;   // 196608 (2-stage, 6 tiles)
    cudaFuncSetAttribute(gemm_mma1, cudaFuncAttributeMaxDynamicSharedMemorySize, SMEM1);
    cudaFuncSetAttribute(gemm_dual, cudaFuncAttributeMaxDynamicSharedMemorySize, SMEMD);

    // 1) weight splits + bias matvec
    split2_k<<<512, 256>>>((const float4*)Wr, Wr_h, Wr_l, DD * HH / 4);
    split2_k<<<512, 256>>>((const float4*)Wq, Wq_h, Wq_l, DD * HH / 4);
    matvec_k<<<DD, 256>>>(Wq, br, v, HH);
    // 2) fused activation prep (single pass over region and query)
    region_prep_k<<<BB * RR, 256>>>(region, Ws, rf_h, rf_l, rd0);
    query_prep_k<<<BB * TT, 256>>>(query, v, Ws + DD, Ws + 2 * DD,
                                   qe_h, qe_l, qe2_h, qe2_l, qv, y1);
    // 3) M2[d,e] = sum_h Wr[d,h] Wq[e,h]  (e contiguous), split output
    gemm_mma1<<<dim3(DD / 128, DD / 128, 1), 256, SMEM1>>>(
        Wr_h, Wr_l, Wq_h, Wq_l, M2_h, M2_l, HH, 0, 0, 0, DD);
    // 4) Nt[b][t,d] = sum_e qe[b,t,e] M2[d,e]  (d contiguous), split output
    gemm_mma1<<<dim3(DD / 128, TT / 128, BB), 256, SMEM1>>>(
        qe_h, qe_l, M2_h, M2_l, Nt_h, Nt_l,
        DD, (size_t)TT * DD, 0, (size_t)TT * DD, DD);
    // 5+6) fused dual GEMM: scores = rf@Nt^T, G = rf@qe2^T (shared A)
    gemm_dual<<<dim3(TT / 128, RR / 128, BB), 256, SMEMD>>>(
        rf_h, rf_l, Nt_h, Nt_l, qe2_h, qe2_l, scores, G,
        DD, (size_t)RR * DD, (size_t)TT * DD, (size_t)RR * TT, TT);
    // 7) fused softmax + weighted sum + final output
    softmax_out<<<BB * RR, 256>>>(scores, G, qv, y1, rd0, bs, out);
}

// round 10
// speedup vs baseline: 1.1546x; 1.0320x over previous
#include <cuda_runtime.h>
#include <cuda_bf16.h>

#define BB 16
#define RR 1024
#define TT 512
#define DD 1024
#define HH 1024

// ---------------------------------------------------------------------------
// Scratch (device globals — allocations are forbidden)
// ---------------------------------------------------------------------------
__device__ __nv_bfloat16 g_Wr_h[DD * HH], g_Wr_l[DD * HH];
__device__ __nv_bfloat16 g_Wq_h[DD * HH], g_Wq_l[DD * HH];
__device__ __nv_bfloat16 g_M2_h[DD * DD], g_M2_l[DD * DD];       // M2[d,e] = sum_h Wr[d,h]Wq[e,h]
__device__ __nv_bfloat16 g_rf_h[(size_t)BB * RR * DD], g_rf_l[(size_t)BB * RR * DD];
__device__ __nv_bfloat16 g_qe_h[(size_t)BB * TT * DD], g_qe_l[(size_t)BB * TT * DD];
__device__ __nv_bfloat16 g_qe2_h[(size_t)BB * TT * DD], g_qe2_l[(size_t)BB * TT * DD]; // qe*Ws2
__device__ __nv_bfloat16 g_Nt_h[(size_t)BB * TT * DD], g_Nt_l[(size_t)BB * TT * DD];   // Nt[b][t,d]
__device__ float         g_scores[(size_t)BB * RR * TT];
__device__ float         g_G[(size_t)BB * RR * TT];
__device__ float         g_v[DD];
__device__ float         g_qv[BB * TT];
__device__ float         g_y1[BB * TT];
__device__ float         g_rd0[BB * RR];

// ---------------------------------------------------------------------------
// PTX helpers (sm_80-level features only: ldmatrix, cp.async, mma.sync)
// ---------------------------------------------------------------------------
__device__ __forceinline__ unsigned smem_u32(const void* p) {
    unsigned a;
    asm("{ .reg .u64 t; cvta.to.shared.u64 t, %1; cvt.u32.u64 %0, t; }" : "=r"(a) : "l"(p));
    return a;
}

#define CP_ASYNC16(dst, src) \
    asm volatile("cp.async.cg.shared.global [%0], [%1], 16;" :: "r"(dst), "l"(src))
#define CP_COMMIT() asm volatile("cp.async.commit_group;" ::: "memory")
#define CP_WAIT0()  asm volatile("cp.async.wait_group 0;" ::: "memory")
#define CP_WAIT1()  asm volatile("cp.async.wait_group 1;" ::: "memory")

__device__ __forceinline__ void ldsm4(unsigned* r, unsigned addr) {
    asm volatile("ldmatrix.sync.aligned.m8n8.x4.shared.b16 {%0,%1,%2,%3}, [%4];"
                 : "=r"(r[0]), "=r"(r[1]), "=r"(r[2]), "=r"(r[3]) : "r"(addr));
}

__device__ __forceinline__ void mma_bf16(float* c, const unsigned* a, const unsigned* b) {
    asm volatile(
        "mma.sync.aligned.m16n8k16.row.col.f32.bf16.bf16.f32 "
        "{%0,%1,%2,%3}, {%4,%5,%6,%7}, {%8,%9}, {%0,%1,%2,%3};"
        : "+f"(c[0]), "+f"(c[1]), "+f"(c[2]), "+f"(c[3])
        : "r"(a[0]), "r"(a[1]), "r"(a[2]), "r"(a[3]), "r"(b[0]), "r"(b[1]));
}

__device__ __forceinline__ unsigned swz(unsigned off) {
    return off ^ ((off >> 3) & 0x70);
}

// ---------------------------------------------------------------------------
// Split-bf16 GEMM, CTA tile 64x128 (8 warps = 2M x 4N, warp tile 32x32).
// 3 terms: hh + hl + lh. K chunks of 64 bf16 (SW128), 3-stage cp.async.
// Split hi/lo bf16 output. Used for M2 and Nt.
// Stage: Ah(8K), Al(8K), Bh(16K), Bl(16K) = 48 KB.
// ---------------------------------------------------------------------------
__global__ void __launch_bounds__(256) gemm_mma1(
    const __nv_bfloat16* __restrict__ A0, const __nv_bfloat16* __restrict__ A1,
    const __nv_bfloat16* __restrict__ B0, const __nv_bfloat16* __restrict__ B1,
    __nv_bfloat16* __restrict__ Ch, __nv_bfloat16* __restrict__ Cl,
    int K, size_t sA, size_t sB, size_t sC, int ldc)
{
    constexpr unsigned TA = 64 * 128;     // 8 KB per A split tile
    constexpr unsigned TB = 128 * 128;    // 16 KB per B split tile
    constexpr unsigned STAGE = 2 * TA + 2 * TB;   // 48 KB

    extern __shared__ char smem[];
    const unsigned sbase = smem_u32(smem);

    const int tid = threadIdx.x;
    const int lid = tid & 31;
    const int wid = tid >> 5;
    const int wm = wid & 1;        // M slab (32 rows)
    const int wn = wid >> 1;       // N slab (32 cols)

    const size_t zb = blockIdx.z;
    const __nv_bfloat16* AP[2] = { A0 + zb * sA, A1 + zb * sA };
    const __nv_bfloat16* BP[2] = { B0 + zb * sB, B1 + zb * sB };
    const size_t rm0 = (size_t)blockIdx.y * 64;
    const size_t rn0 = (size_t)blockIdx.x * 128;
    const int NC = K >> 6;

    float c[2][4][4] = {};

    const int al_r  = lid & 15;
    const int al_k  = (lid >> 4) & 1;
    const int bl_r  = (lid & 7) + ((lid >> 4) << 3);
    const int bl_k  = (lid >> 3) & 1;

    auto load_stage = [&](int st, int ck) {
        const unsigned sdst = sbase + (unsigned)st * STAGE;
        const int k0 = ck << 6;
        #pragma unroll
        for (int sp = 0; sp < 2; sp++) {
            #pragma unroll
            for (int i = 0; i < 2; i++) {       // A: 64 rows
                int idx = i * 256 + tid;
                int row = idx >> 3, g = idx & 7;
                const __nv_bfloat16* gs = AP[sp] + (rm0 + row) * (size_t)K + k0 + g * 8;
                unsigned d = sdst + (unsigned)sp * TA + swz((unsigned)(row * 128 + g * 16));
                CP_ASYNC16(d, gs);
            }
        }
        #pragma unroll
        for (int sp = 0; sp < 2; sp++) {
            #pragma unroll
            for (int i = 0; i < 4; i++) {       // B: 128 rows
                int idx = i * 256 + tid;
                int row = idx >> 3, g = idx & 7;
                const __nv_bfloat16* gs = BP[sp] + (rn0 + row) * (size_t)K + k0 + g * 8;
                unsigned d = sdst + 2 * TA + (unsigned)sp * TB +
                             swz((unsigned)(row * 128 + g * 16));
                CP_ASYNC16(d, gs);
            }
        }
    };

    load_stage(0, 0); CP_COMMIT();
    load_stage(1, 1); CP_COMMIT();

    for (int ck = 0; ck < NC; ck++) {
        if (ck + 1 < NC) CP_WAIT1(); else CP_WAIT0();
        __syncthreads();
        if (ck + 2 < NC) {
            load_stage((ck + 2) % 3, ck + 2);
            CP_COMMIT();
        }

        const unsigned sb2 = sbase + (unsigned)(ck % 3) * STAGE;
        #pragma unroll
        for (int ks = 0; ks < 4; ks++) {
            unsigned af[2][2][4];
            unsigned bf[2][4][2];
            #pragma unroll
            for (int sp = 0; sp < 2; sp++) {
                #pragma unroll
                for (int mt = 0; mt < 2; mt++) {
                    unsigned addr = sb2 + (unsigned)sp * TA +
                        swz((unsigned)((wm * 32 + mt * 16 + al_r) * 128 + ks * 32 + al_k * 16));
                    ldsm4(af[sp][mt], addr);
                }
                #pragma unroll
                for (int np = 0; np < 2; np++) {
                    unsigned r[4];
                    unsigned addr = sb2 + 2 * TA + (unsigned)sp * TB +
                        swz((unsigned)((wn * 32 + np * 16 + bl_r) * 128 + ks * 32 + bl_k * 16));
                    ldsm4(r, addr);
                    bf[sp][2 * np][0] = r[0]; bf[sp][2 * np][1] = r[1];
                    bf[sp][2 * np + 1][0] = r[2]; bf[sp][2 * np + 1][1] = r[3];
                }
            }
            #pragma unroll
            for (int tm = 0; tm < 3; tm++) {
                const int i = (tm == 2) ? 1 : 0;
                const int j = (tm == 1) ? 1 : 0;
                #pragma unroll
                for (int mt = 0; mt < 2; mt++)
                    #pragma unroll
                    for (int nt = 0; nt < 4; nt++)
                        mma_bf16(c[mt][nt], af[i][mt], bf[j][nt]);
            }
        }
    }
    __syncthreads();

    const int qr = lid >> 2;
    const int qc = (lid & 3) * 2;
    #pragma unroll
    for (int mt = 0; mt < 2; mt++) {
        #pragma unroll
        for (int nt = 0; nt < 4; nt++) {
            size_t gr = rm0 + wm * 32 + mt * 16 + qr;
            int gc = (int)rn0 + wn * 32 + nt * 8 + qc;
            #pragma unroll
            for (int half = 0; half < 2; half++) {
                float v0 = c[mt][nt][2 * half + 0];
                float v1 = c[mt][nt][2 * half + 1];
                size_t o = zb * sC + (gr + half * 8) * (size_t)ldc + gc;
                __nv_bfloat162 hv, lv;
                hv.x = __float2bfloat16(v0);
                hv.y = __float2bfloat16(v1);
                lv.x = __float2bfloat16(v0 - __bfloat162float(hv.x));
                lv.y = __float2bfloat16(v1 - __bfloat162float(hv.y));
                *reinterpret_cast<__nv_bfloat162*>(Ch + o) = hv;
                *reinterpret_cast<__nv_bfloat162*>(Cl + o) = lv;
            }
        }
    }
}

// ---------------------------------------------------------------------------
// Dual-B GEMM, CTA tile 64x128: shared A (rf), two B operands (Nt, qe2),
// two fp32 outputs (scores, G). 2-stage pipeline, 80 KB/stage.
// ---------------------------------------------------------------------------
__global__ void __launch_bounds__(256) gemm_dual(
    const __nv_bfloat16* __restrict__ A0, const __nv_bfloat16* __restrict__ A1,
    const __nv_bfloat16* __restrict__ B0, const __nv_bfloat16* __restrict__ B1,
    const __nv_bfloat16* __restrict__ C0, const __nv_bfloat16* __restrict__ C1,
    float* __restrict__ S, float* __restrict__ G,
    int K, size_t sA, size_t sB, size_t sC, int ldc)
{
    constexpr unsigned TA = 64 * 128;     // 8 KB
    constexpr unsigned TB = 128 * 128;    // 16 KB
    constexpr unsigned STAGE = 2 * TA + 4 * TB;   // 80 KB

    extern __shared__ char smem[];
    const unsigned sbase = smem_u32(smem);

    const int tid = threadIdx.x;
    const int lid = tid & 31;
    const int wid = tid >> 5;
    const int wm = wid & 1;
    const int wn = wid >> 1;

    const size_t zb = blockIdx.z;
    const __nv_bfloat16* AP[2] = { A0 + zb * sA, A1 + zb * sA };
    const __nv_bfloat16* BP[4] = { B0 + zb * sB, B1 + zb * sB,
                                   C0 + zb * sB, C1 + zb * sB };
    const size_t rm0 = (size_t)blockIdx.y * 64;
    const size_t rn0 = (size_t)blockIdx.x * 128;
    const int NC = K >> 6;

    float c1[2][4][4] = {};
    float c2[2][4][4] = {};

    const int al_r  = lid & 15;
    const int al_k  = (lid >> 4) & 1;
    const int bl_r  = (lid & 7) + ((lid >> 4) << 3);
    const int bl_k  = (lid >> 3) & 1;

    auto load_stage = [&](int st, int ck) {
        const unsigned sdst = sbase + (unsigned)st * STAGE;
        const int k0 = ck << 6;
        #pragma unroll
        for (int sp = 0; sp < 2; sp++) {
            #pragma unroll
            for (int i = 0; i < 2; i++) {       // A: 64 rows
                int idx = i * 256 + tid;
                int row = idx >> 3, g = idx & 7;
                const __nv_bfloat16* gs = AP[sp] + (rm0 + row) * (size_t)K + k0 + g * 8;
                unsigned d = sdst + (unsigned)sp * TA + swz((unsigned)(row * 128 + g * 16));
                CP_ASYNC16(d, gs);
            }
        }
        #pragma unroll
        for (int t4 = 0; t4 < 4; t4++) {
            #pragma unroll
            for (int i = 0; i < 4; i++) {       // B: 128 rows
                int idx = i * 256 + tid;
                int row = idx >> 3, g = idx & 7;
                const __nv_bfloat16* gs = BP[t4] + (rn0 + row) * (size_t)K + k0 + g * 8;
                unsigned d = sdst + 2 * TA + (unsigned)t4 * TB +
                             swz((unsigned)(row * 128 + g * 16));
                CP_ASYNC16(d, gs);
            }
        }
    };

    load_stage(0, 0); CP_COMMIT();

    for (int ck = 0; ck < NC; ck++) {
        if (ck + 1 < NC) {
            load_stage((ck + 1) & 1, ck + 1);
            CP_COMMIT();
            CP_WAIT1();
        } else {
            CP_WAIT0();
        }
        __syncthreads();

        const unsigned sb2 = sbase + (unsigned)(ck & 1) * STAGE;
        #pragma unroll
        for (int ks = 0; ks < 4; ks++) {
            unsigned af[2][2][4];
            #pragma unroll
            for (int sp = 0; sp < 2; sp++)
                #pragma unroll
                for (int mt = 0; mt < 2; mt++) {
                    unsigned addr = sb2 + (unsigned)sp * TA +
                        swz((unsigned)((wm * 32 + mt * 16 + al_r) * 128 + ks * 32 + al_k * 16));
                    ldsm4(af[sp][mt], addr);
                }
            // ---- product 1: B = Nt (tiles 0,1) -> c1
            {
                unsigned bf[2][4][2];
                #pragma unroll
                for (int sp = 0; sp < 2; sp++)
                    #pragma unroll
                    for (int np = 0; np < 2; np++) {
                        unsigned r[4];
                        unsigned addr = sb2 + 2 * TA + (unsigned)sp * TB +
                            swz((unsigned)((wn * 32 + np * 16 + bl_r) * 128 + ks * 32 + bl_k * 16));
                        ldsm4(r, addr);
                        bf[sp][2 * np][0] = r[0]; bf[sp][2 * np][1] = r[1];
                        bf[sp][2 * np + 1][0] = r[2]; bf[sp][2 * np + 1][1] = r[3];
                    }
                #pragma unroll
                for (int tm = 0; tm < 3; tm++) {
                    const int i = (tm == 2) ? 1 : 0;
                    const int j = (tm == 1) ? 1 : 0;
                    #pragma unroll
                    for (int mt = 0; mt < 2; mt++)
                        #pragma unroll
                        for (int nt = 0; nt < 4; nt++)
                            mma_bf16(c1[mt][nt], af[i][mt], bf[j][nt]);
                }
            }
            // ---- product 2: B = qe2 (tiles 2,3) -> c2
            {
                unsigned bf[2][4][2];
                #pragma unroll
                for (int sp = 0; sp < 2; sp++)
                    #pragma unroll
                    for (int np = 0; np < 2; np++) {
                        unsigned r[4];
                        unsigned addr = sb2 + 2 * TA + (unsigned)(2 + sp) * TB +
                            swz((unsigned)((wn * 32 + np * 16 + bl_r) * 128 + ks * 32 + bl_k * 16));
                        ldsm4(r, addr);
                        bf[sp][2 * np][0] = r[0]; bf[sp][2 * np][1] = r[1];
                        bf[sp][2 * np + 1][0] = r[2]; bf[sp][2 * np + 1][1] = r[3];
                    }
                #pragma unroll
                for (int tm = 0; tm < 3; tm++) {
                    const int i = (tm == 2) ? 1 : 0;
                    const int j = (tm == 1) ? 1 : 0;
                    #pragma unroll
                    for (int mt = 0; mt < 2; mt++)
                        #pragma unroll
                        for (int nt = 0; nt < 4; nt++)
                            mma_bf16(c2[mt][nt], af[i][mt], bf[j][nt]);
                }
            }
        }
        __syncthreads();
    }

    const int qr = lid >> 2;
    const int qc = (lid & 3) * 2;
    #pragma unroll
    for (int mt = 0; mt < 2; mt++) {
        #pragma unroll
        for (int nt = 0; nt < 4; nt++) {
            size_t gr = rm0 + wm * 32 + mt * 16 + qr;
            int gc = (int)rn0 + wn * 32 + nt * 8 + qc;
            #pragma unroll
            for (int half = 0; half < 2; half++) {
                size_t o = zb * sC + (gr + half * 8) * (size_t)ldc + gc;
                *reinterpret_cast<float2*>(S + o) =
                    make_float2(c1[mt][nt][2 * half], c1[mt][nt][2 * half + 1]);
                *reinterpret_cast<float2*>(G + o) =
                    make_float2(c2[mt][nt][2 * half], c2[mt][nt][2 * half + 1]);
            }
        }
    }
}

// ---------------------------------------------------------------------------
// fp32 -> 2-way bf16 split (elementwise, vectorized) — for weights
// ---------------------------------------------------------------------------
__global__ void __launch_bounds__(256) split2_k(
    const float4* __restrict__ x, __nv_bfloat16* __restrict__ h,
    __nv_bfloat16* __restrict__ l, int n4)
{
    for (int i = blockIdx.x * blockDim.x + threadIdx.x; i < n4;
         i += gridDim.x * blockDim.x) {
        float4 v = x[i];
        float a[4] = {v.x, v.y, v.z, v.w};
        __nv_bfloat16 hh[4], ll[4];
        #pragma unroll
        for (int k = 0; k < 4; k++) {
            hh[k] = __float2bfloat16(a[k]);
            ll[k] = __float2bfloat16(a[k] - __bfloat162float(hh[k]));
        }
        __nv_bfloat162 p0, p1;
        p0.x = hh[0]; p0.y = hh[1]; p1.x = hh[2]; p1.y = hh[3];
        reinterpret_cast<__nv_bfloat162*>(h)[2 * i] = p0;
        reinterpret_cast<__nv_bfloat162*>(h)[2 * i + 1] = p1;
        p0.x = ll[0]; p0.y = ll[1]; p1.x = ll[2]; p1.y = ll[3];
        reinterpret_cast<__nv_bfloat162*>(l)[2 * i] = p0;
        reinterpret_cast<__nv_bfloat162*>(l)[2 * i + 1] = p1;
    }
}

// ---------------------------------------------------------------------------
// region prep: one CTA per (b,r) row. Writes rf_h/rf_l; computes rd0 = row.Ws0.
// ---------------------------------------------------------------------------
__global__ void __launch_bounds__(256) region_prep_k(
    const float* __restrict__ region, const float* __restrict__ Ws0,
    __nv_bfloat16* __restrict__ rf_h, __nv_bfloat16* __restrict__ rf_l,
    float* __restrict__ rd0)
{
    size_t row = blockIdx.x;
    int t = threadIdx.x;
    float4 a = *reinterpret_cast<const float4*>(region + row * DD + t * 4);
    float4 w = *reinterpret_cast<const float4*>(Ws0 + t * 4);

    __nv_bfloat162 h0, h1, l0, l1;
    h0.x = __float2bfloat16(a.x); h0.y = __float2bfloat16(a.y);
    h1.x = __float2bfloat16(a.z); h1.y = __float2bfloat16(a.w);
    l0.x = __float2bfloat16(a.x - __bfloat162float(h0.x));
    l0.y = __float2bfloat16(a.y - __bfloat162float(h0.y));
    l1.x = __float2bfloat16(a.z - __bfloat162float(h1.x));
    l1.y = __float2bfloat16(a.w - __bfloat162float(h1.y));
    reinterpret_cast<__nv_bfloat162*>(rf_h + row * DD)[2 * t] = h0;
    reinterpret_cast<__nv_bfloat162*>(rf_h + row * DD)[2 * t + 1] = h1;
    reinterpret_cast<__nv_bfloat162*>(rf_l + row * DD)[2 * t] = l0;
    reinterpret_cast<__nv_bfloat162*>(rf_l + row * DD)[2 * t + 1] = l1;

    float p = a.x * w.x + a.y * w.y + a.z * w.z + a.w * w.w;
    __shared__ float red[8];
    #pragma unroll
    for (int o = 16; o; o >>= 1) p += __shfl_xor_sync(0xffffffffu, p, o);
    if ((t & 31) == 0) red[t >> 5] = p;
    __syncthreads();
    if (t == 0) {
        float s = 0.f;
        #pragma unroll
        for (int i = 0; i < 8; i++) s += red[i];
        rd0[row] = s;
    }
}

// ---------------------------------------------------------------------------
// query prep: one CTA per (b,t) row. Writes qe_h/l and qe2_h/l (= qe*Ws2);
// computes qv = row.v and y1 = row.Ws1.
// ---------------------------------------------------------------------------
__global__ void __launch_bounds__(256) query_prep_k(
    const float* __restrict__ query, const float* __restrict__ v,
    const float* __restrict__ Ws1, const float* __restrict__ Ws2,
    __nv_bfloat16* __restrict__ qe_h, __nv_bfloat16* __restrict__ qe_l,
    __nv_bfloat16* __restrict__ qe2_h, __nv_bfloat16* __restrict__ qe2_l,
    float* __restrict__ qv, float* __restrict__ y1)
{
    size_t row = blockIdx.x;
    int t = threadIdx.x;
    float4 a = *reinterpret_cast<const float4*>(query + row * DD + t * 4);
    float4 vv = *reinterpret_cast<const float4*>(v + t * 4);
    float4 w1 = *reinterpret_cast<const float4*>(Ws1 + t * 4);
    float4 w2 = *reinterpret_cast<const float4*>(Ws2 + t * 4);

    __nv_bfloat162 h0, h1, l0, l1;
    h0.x = __float2bfloat16(a.x); h0.y = __float2bfloat16(a.y);
    h1.x = __float2bfloat16(a.z); h1.y = __float2bfloat16(a.w);
    l0.x = __float2bfloat16(a.x - __bfloat162float(h0.x));
    l0.y = __float2bfloat16(a.y - __bfloat162float(h0.y));
    l1.x = __float2bfloat16(a.z - __bfloat162float(h1.x));
    l1.y = __float2bfloat16(a.w - __bfloat162float(h1.y));
    reinterpret_cast<__nv_bfloat162*>(qe_h + row * DD)[2 * t] = h0;
    reinterpret_cast<__nv_bfloat162*>(qe_h + row * DD)[2 * t + 1] = h1;
    reinterpret_cast<__nv_bfloat162*>(qe_l + row * DD)[2 * t] = l0;
    reinterpret_cast<__nv_bfloat162*>(qe_l + row * DD)[2 * t + 1] = l1;

    float b0 = a.x * w2.x, b1 = a.y * w2.y, b2 = a.z * w2.z, b3 = a.w * w2.w;
    h0.x = __float2bfloat16(b0); h0.y = __float2bfloat16(b1);
    h1.x = __float2bfloat16(b2); h1.y = __float2bfloat16(b3);
    l0.x = __float2bfloat16(b0 - __bfloat162float(h0.x));
    l0.y = __float2bfloat16(b1 - __bfloat162float(h0.y));
    l1.x = __float2bfloat16(b2 - __bfloat162float(h1.x));
    l1.y = __float2bfloat16(b3 - __bfloat162float(h1.y));
    reinterpret_cast<__nv_bfloat162*>(qe2_h + row * DD)[2 * t] = h0;
    reinterpret_cast<__nv_bfloat162*>(qe2_h + row * DD)[2 * t + 1] = h1;
    reinterpret_cast<__nv_bfloat162*>(qe2_l + row * DD)[2 * t] = l0;
    reinterpret_cast<__nv_bfloat162*>(qe2_l + row * DD)[2 * t + 1] = l1;

    float p = a.x * vv.x + a.y * vv.y + a.z * vv.z + a.w * vv.w;
    float q = a.x * w1.x + a.y * w1.y + a.z * w1.z + a.w * w1.w;
    __shared__ float red[16];
    #pragma unroll
    for (int o = 16; o; o >>= 1) {
        p += __shfl_xor_sync(0xffffffffu, p, o);
        q += __shfl_xor_sync(0xffffffffu, q, o);
    }
    if ((t & 31) == 0) { red[t >> 5] = p; red[8 + (t >> 5)] = q; }
    __syncthreads();
    if (t == 0) {
        float s = 0.f, s2 = 0.f;
        #pragma unroll
        for (int i = 0; i < 8; i++) { s += red[i]; s2 += red[8 + i]; }
        qv[row] = s;
        y1[row] = s2;
    }
}

// ---------------------------------------------------------------------------
// v[d] = sum_h Wq[d,h] * br[h]
// ---------------------------------------------------------------------------
__global__ void __launch_bounds__(256) matvec_k(
    const float* __restrict__ W, const float* __restrict__ b,
    float* __restrict__ v, int H)
{
    const float* row = W + (size_t)blockIdx.x * H;
    int t = threadIdx.x;
    float p = 0.f;
    for (int h = t * 4; h < H; h += 1024) {
        float4 wv = *reinterpret_cast<const float4*>(row + h);
        float4 bv = *reinterpret_cast<const float4*>(b + h);
        p = fmaf(wv.x, bv.x, p); p = fmaf(wv.y, bv.y, p);
        p = fmaf(wv.z, bv.z, p); p = fmaf(wv.w, bv.w, p);
    }
    __shared__ float red[8];
    #pragma unroll
    for (int o = 16; o; o >>= 1) p += __shfl_xor_sync(0xffffffffu, p, o);
    if ((t & 31) == 0) red[t >> 5] = p;
    __syncthreads();
    if (t == 0) {
        float s = 0.f;
        #pragma unroll
        for (int i = 0; i < 8; i++) s += red[i];
        v[blockIdx.x] = s;
    }
}

// ---------------------------------------------------------------------------
// Fused softmax + weighted reduction:
// out[b,r] = rd0[b,r] + sum_t softmax(scores[b,r,:]+qv[b,:])[t] * (y1[b,t]+G[b,r,t]) + bs
// ---------------------------------------------------------------------------
__global__ void __launch_bounds__(256) softmax_out(
    const float* __restrict__ S, const float* __restrict__ G,
    const float* __restrict__ qv, const float* __restrict__ y1,
    const float* __restrict__ rd0, const float* __restrict__ bs,
    float* __restrict__ out)
{
    size_t rowi = blockIdx.x;
    const float* row = S + rowi * TT;
    const float* grow = G + rowi * TT;
    size_t boff = (rowi / RR) * TT;
    int t = threadIdx.x;
    float v0 = row[t] + qv[boff + t];
    float v1 = row[t + 256] + qv[boff + t + 256];

    __shared__ float red[16];

    float m = fmaxf(v0, v1);
    #pragma unroll
    for (int o = 16; o; o >>= 1) m = fmaxf(m, __shfl_xor_sync(0xffffffffu, m, o));
    if ((t & 31) == 0) red[t >> 5] = m;
    __syncthreads();
    if (t == 0) {
        float x = red[0];
        #pragma unroll
        for (int i = 1; i < 8; i++) x = fmaxf(x, red[i]);
        red[0] = x;
    }
    __syncthreads();
    m = red[0];
    __syncthreads();

    float e0 = expf(v0 - m);
    float e1 = expf(v1 - m);
    float den = e0 + e1;
    float num = e0 * (y1[boff + t] + grow[t]) +
                e1 * (y1[boff + t + 256] + grow[t + 256]);
    #pragma unroll
    for (int o = 16; o; o >>= 1) {
        den += __shfl_xor_sync(0xffffffffu, den, o);
        num += __shfl_xor_sync(0xffffffffu, num, o);
    }
    if ((t & 31) == 0) { red[t >> 5] = den; red[8 + (t >> 5)] = num; }
    __syncthreads();
    if (t == 0) {
        float sd = 0.f, sn = 0.f;
        #pragma unroll
        for (int i = 0; i < 8; i++) { sd += red[i]; sn += red[8 + i]; }
        out[rowi] = rd0[rowi] + sn / sd + bs[0];
    }
}

// ---------------------------------------------------------------------------
extern "C" void kernel_launch(void* const* d_in, const int* in_sizes, int n_in,
                              void* d_out, int out_size)
{
    const float* region = (const float*)d_in[0];
    const float* query  = (const float*)d_in[1];
    const float* Wr     = (const float*)d_in[2];
    const float* br     = (const float*)d_in[3];
    const float* Wq     = (const float*)d_in[4];
    const float* bq     = (const float*)d_in[5];
    const float* Ws     = (const float*)d_in[6];
    const float* bs     = (const float*)d_in[7];
    float* out = (float*)d_out;
    (void)bq;  // softmax-invariant terms drop out

    __nv_bfloat16 *Wr_h, *Wr_l, *Wq_h, *Wq_l, *M2_h, *M2_l;
    __nv_bfloat16 *rf_h, *rf_l, *qe_h, *qe_l, *qe2_h, *qe2_l, *Nt_h, *Nt_l;
    float *scores, *G, *v, *qv, *y1, *rd0;
    cudaGetSymbolAddress((void**)&Wr_h, g_Wr_h);
    cudaGetSymbolAddress((void**)&Wr_l, g_Wr_l);
    cudaGetSymbolAddress((void**)&Wq_h, g_Wq_h);
    cudaGetSymbolAddress((void**)&Wq_l, g_Wq_l);
    cudaGetSymbolAddress((void**)&M2_h, g_M2_h);
    cudaGetSymbolAddress((void**)&M2_l, g_M2_l);
    cudaGetSymbolAddress((void**)&rf_h, g_rf_h);
    cudaGetSymbolAddress((void**)&rf_l, g_rf_l);
    cudaGetSymbolAddress((void**)&qe_h, g_qe_h);
    cudaGetSymbolAddress((void**)&qe_l, g_qe_l);
    cudaGetSymbolAddress((void**)&qe2_h, g_qe2_h);
    cudaGetSymbolAddress((void**)&qe2_l, g_qe2_l);
    cudaGetSymbolAddress((void**)&Nt_h, g_Nt_h);
    cudaGetSymbolAddress((void**)&Nt_l, g_Nt_l);
    cudaGetSymbolAddress((void**)&scores, g_scores);
    cudaGetSymbolAddress((void**)&G, g_G);
    cudaGetSymbolAddress((void**)&v, g_v);
    cudaGetSymbolAddress((void**)&qv, g_qv);
    cudaGetSymbolAddress((void**)&y1, g_y1);
    cudaGetSymbolAddress((void**)&rd0, g_rd0);

    const int SMEM1 = 3 * (2 * 8192 + 2 * 16384);       // 147456 (3-stage, 48KB)
    const int SMEMD = 2 * (2 * 8192 + 4 * 16384);       // 163840 (2-stage, 80KB)
    cudaFuncSetAttribute(gemm_mma1, cudaFuncAttributeMaxDynamicSharedMemorySize, SMEM1);
    cudaFuncSetAttribute(gemm_dual, cudaFuncAttributeMaxDynamicSharedMemorySize, SMEMD);

    // 1) weight splits + bias matvec
    split2_k<<<512, 256>>>((const float4*)Wr, Wr_h, Wr_l, DD * HH / 4);
    split2_k<<<512, 256>>>((const float4*)Wq, Wq_h, Wq_l, DD * HH / 4);
    matvec_k<<<DD, 256>>>(Wq, br, v, HH);
    // 2) fused activation prep (single pass over region and query)
    region_prep_k<<<BB * RR, 256>>>(region, Ws, rf_h, rf_l, rd0);
    query_prep_k<<<BB * TT, 256>>>(query, v, Ws + DD, Ws + 2 * DD,
                                   qe_h, qe_l, qe2_h, qe2_l, qv, y1);
    // 3) M2[d,e] = sum_h Wr[d,h] Wq[e,h]  (e contiguous), split output
    gemm_mma1<<<dim3(DD / 128, DD / 64, 1), 256, SMEM1>>>(
        Wr_h, Wr_l, Wq_h, Wq_l, M2_h, M2_l, HH, 0, 0, 0, DD);
    // 4) Nt[b][t,d] = sum_e qe[b,t,e] M2[d,e]  (d contiguous), split output
    gemm_mma1<<<dim3(DD / 128, TT / 64, BB), 256, SMEM1>>>(
        qe_h, qe_l, M2_h, M2_l, Nt_h, Nt_l,
        DD, (size_t)TT * DD, 0, (size_t)TT * DD, DD);
    // 5+6) fused dual GEMM: scores = rf@Nt^T, G = rf@qe2^T (shared A)
    gemm_dual<<<dim3(TT / 128, RR / 64, BB), 256, SMEMD>>>(
        rf_h, rf_l, Nt_h, Nt_l, qe2_h, qe2_l, scores, G,
        DD, (size_t)RR * DD, (size_t)TT * DD, (size_t)RR * TT, TT);
    // 7) fused softmax + weighted sum + final output
    softmax_out<<<BB * RR, 256>>>(scores, G, qv, y1, rd0, bs, out);
}

// round 11
// speedup vs baseline: 1.2108x; 1.0487x over previous
#include <cuda_runtime.h>
#include <cuda_bf16.h>

#define BB 16
#define RR 1024
#define TT 512
#define DD 1024
#define HH 1024

// ---------------------------------------------------------------------------
// Scratch (device globals — allocations are forbidden)
// ---------------------------------------------------------------------------
__device__ __nv_bfloat16 g_Wr_h[DD * HH], g_Wr_l[DD * HH];
__device__ __nv_bfloat16 g_Wq_h[DD * HH], g_Wq_l[DD * HH];
__device__ __nv_bfloat16 g_M2_h[DD * DD], g_M2_l[DD * DD];       // M2[d,e] = sum_h Wr[d,h]Wq[e,h]
__device__ __nv_bfloat16 g_rf_h[(size_t)BB * RR * DD], g_rf_l[(size_t)BB * RR * DD];
__device__ __nv_bfloat16 g_qe_h[(size_t)BB * TT * DD], g_qe_l[(size_t)BB * TT * DD];
__device__ __nv_bfloat16 g_qe2_h[(size_t)BB * TT * DD], g_qe2_l[(size_t)BB * TT * DD]; // qe*Ws2
__device__ __nv_bfloat16 g_Nt_h[(size_t)BB * TT * DD], g_Nt_l[(size_t)BB * TT * DD];   // Nt[b][t,d]
__device__ float4        g_part[(size_t)BB * RR * 4];   // (m, den, num, pad) per t-slice
__device__ float         g_v[DD];
__device__ float         g_qv[BB * TT];
__device__ float         g_y1[BB * TT];
__device__ float         g_rd0[BB * RR];

// ---------------------------------------------------------------------------
// PTX helpers (sm_80-level features only: ldmatrix, cp.async, mma.sync)
// ---------------------------------------------------------------------------
__device__ __forceinline__ unsigned smem_u32(const void* p) {
    unsigned a;
    asm("{ .reg .u64 t; cvta.to.shared.u64 t, %1; cvt.u32.u64 %0, t; }" : "=r"(a) : "l"(p));
    return a;
}

#define CP_ASYNC16(dst, src) \
    asm volatile("cp.async.cg.shared.global [%0], [%1], 16;" :: "r"(dst), "l"(src))
#define CP_COMMIT() asm volatile("cp.async.commit_group;" ::: "memory")
#define CP_WAIT0()  asm volatile("cp.async.wait_group 0;" ::: "memory")
#define CP_WAIT1()  asm volatile("cp.async.wait_group 1;" ::: "memory")

__device__ __forceinline__ void ldsm4(unsigned* r, unsigned addr) {
    asm volatile("ldmatrix.sync.aligned.m8n8.x4.shared.b16 {%0,%1,%2,%3}, [%4];"
                 : "=r"(r[0]), "=r"(r[1]), "=r"(r[2]), "=r"(r[3]) : "r"(addr));
}

__device__ __forceinline__ void mma_bf16(float* c, const unsigned* a, const unsigned* b) {
    asm volatile(
        "mma.sync.aligned.m16n8k16.row.col.f32.bf16.bf16.f32 "
        "{%0,%1,%2,%3}, {%4,%5,%6,%7}, {%8,%9}, {%0,%1,%2,%3};"
        : "+f"(c[0]), "+f"(c[1]), "+f"(c[2]), "+f"(c[3])
        : "r"(a[0]), "r"(a[1]), "r"(a[2]), "r"(a[3]), "r"(b[0]), "r"(b[1]));
}

__device__ __forceinline__ unsigned swz(unsigned off) {
    return off ^ ((off >> 3) & 0x70);
}

// ---------------------------------------------------------------------------
// Split-bf16 GEMM, CTA tile 64x128 (8 warps = 2M x 4N, warp tile 32x32).
// 3 terms: hh + hl + lh. K chunks of 64 bf16 (SW128), 3-stage cp.async.
// Split hi/lo bf16 output. Used for M2 and Nt.
// ---------------------------------------------------------------------------
__global__ void __launch_bounds__(256) gemm_mma1(
    const __nv_bfloat16* __restrict__ A0, const __nv_bfloat16* __restrict__ A1,
    const __nv_bfloat16* __restrict__ B0, const __nv_bfloat16* __restrict__ B1,
    __nv_bfloat16* __restrict__ Ch, __nv_bfloat16* __restrict__ Cl,
    int K, size_t sA, size_t sB, size_t sC, int ldc)
{
    constexpr unsigned TA = 64 * 128;     // 8 KB per A split tile
    constexpr unsigned TB = 128 * 128;    // 16 KB per B split tile
    constexpr unsigned STAGE = 2 * TA + 2 * TB;   // 48 KB

    extern __shared__ char smem[];
    const unsigned sbase = smem_u32(smem);

    const int tid = threadIdx.x;
    const int lid = tid & 31;
    const int wid = tid >> 5;
    const int wm = wid & 1;
    const int wn = wid >> 1;

    const size_t zb = blockIdx.z;
    const __nv_bfloat16* AP[2] = { A0 + zb * sA, A1 + zb * sA };
    const __nv_bfloat16* BP[2] = { B0 + zb * sB, B1 + zb * sB };
    const size_t rm0 = (size_t)blockIdx.y * 64;
    const size_t rn0 = (size_t)blockIdx.x * 128;
    const int NC = K >> 6;

    float c[2][4][4] = {};

    const int al_r  = lid & 15;
    const int al_k  = (lid >> 4) & 1;
    const int bl_r  = (lid & 7) + ((lid >> 4) << 3);
    const int bl_k  = (lid >> 3) & 1;

    auto load_stage = [&](int st, int ck) {
        const unsigned sdst = sbase + (unsigned)st * STAGE;
        const int k0 = ck << 6;
        #pragma unroll
        for (int sp = 0; sp < 2; sp++) {
            #pragma unroll
            for (int i = 0; i < 2; i++) {
                int idx = i * 256 + tid;
                int row = idx >> 3, g = idx & 7;
                const __nv_bfloat16* gs = AP[sp] + (rm0 + row) * (size_t)K + k0 + g * 8;
                unsigned d = sdst + (unsigned)sp * TA + swz((unsigned)(row * 128 + g * 16));
                CP_ASYNC16(d, gs);
            }
        }
        #pragma unroll
        for (int sp = 0; sp < 2; sp++) {
            #pragma unroll
            for (int i = 0; i < 4; i++) {
                int idx = i * 256 + tid;
                int row = idx >> 3, g = idx & 7;
                const __nv_bfloat16* gs = BP[sp] + (rn0 + row) * (size_t)K + k0 + g * 8;
                unsigned d = sdst + 2 * TA + (unsigned)sp * TB +
                             swz((unsigned)(row * 128 + g * 16));
                CP_ASYNC16(d, gs);
            }
        }
    };

    load_stage(0, 0); CP_COMMIT();
    load_stage(1, 1); CP_COMMIT();

    for (int ck = 0; ck < NC; ck++) {
        if (ck + 1 < NC) CP_WAIT1(); else CP_WAIT0();
        __syncthreads();
        if (ck + 2 < NC) {
            load_stage((ck + 2) % 3, ck + 2);
            CP_COMMIT();
        }

        const unsigned sb2 = sbase + (unsigned)(ck % 3) * STAGE;
        #pragma unroll
        for (int ks = 0; ks < 4; ks++) {
            unsigned af[2][2][4];
            unsigned bf[2][4][2];
            #pragma unroll
            for (int sp = 0; sp < 2; sp++) {
                #pragma unroll
                for (int mt = 0; mt < 2; mt++) {
                    unsigned addr = sb2 + (unsigned)sp * TA +
                        swz((unsigned)((wm * 32 + mt * 16 + al_r) * 128 + ks * 32 + al_k * 16));
                    ldsm4(af[sp][mt], addr);
                }
                #pragma unroll
                for (int np = 0; np < 2; np++) {
                    unsigned r[4];
                    unsigned addr = sb2 + 2 * TA + (unsigned)sp * TB +
                        swz((unsigned)((wn * 32 + np * 16 + bl_r) * 128 + ks * 32 + bl_k * 16));
                    ldsm4(r, addr);
                    bf[sp][2 * np][0] = r[0]; bf[sp][2 * np][1] = r[1];
                    bf[sp][2 * np + 1][0] = r[2]; bf[sp][2 * np + 1][1] = r[3];
                }
            }
            #pragma unroll
            for (int tm = 0; tm < 3; tm++) {
                const int i = (tm == 2) ? 1 : 0;
                const int j = (tm == 1) ? 1 : 0;
                #pragma unroll
                for (int mt = 0; mt < 2; mt++)
                    #pragma unroll
                    for (int nt = 0; nt < 4; nt++)
                        mma_bf16(c[mt][nt], af[i][mt], bf[j][nt]);
            }
        }
    }
    __syncthreads();

    const int qr = lid >> 2;
    const int qc = (lid & 3) * 2;
    #pragma unroll
    for (int mt = 0; mt < 2; mt++) {
        #pragma unroll
        for (int nt = 0; nt < 4; nt++) {
            size_t gr = rm0 + wm * 32 + mt * 16 + qr;
            int gc = (int)rn0 + wn * 32 + nt * 8 + qc;
            #pragma unroll
            for (int half = 0; half < 2; half++) {
                float v0 = c[mt][nt][2 * half + 0];
                float v1 = c[mt][nt][2 * half + 1];
                size_t o = zb * sC + (gr + half * 8) * (size_t)ldc + gc;
                __nv_bfloat162 hv, lv;
                hv.x = __float2bfloat16(v0);
                hv.y = __float2bfloat16(v1);
                lv.x = __float2bfloat16(v0 - __bfloat162float(hv.x));
                lv.y = __float2bfloat16(v1 - __bfloat162float(hv.y));
                *reinterpret_cast<__nv_bfloat162*>(Ch + o) = hv;
                *reinterpret_cast<__nv_bfloat162*>(Cl + o) = lv;
            }
        }
    }
}

// ---------------------------------------------------------------------------
// Dual-B GEMM with fused split-softmax epilogue. CTA tile 64x128.
// c1 = rf@Nt^T (pre-softmax scores slice), c2 = rf@qe2^T (G slice).
// Epilogue: per row, partial softmax over this CTA's 128 t-values:
//   m = max(c1+qv), den = sum exp(.-m), num = sum exp(.-m)*(y1+c2)
// Writes one float4 (m, den, num, 0) per (row, t-slice).
// ---------------------------------------------------------------------------
__global__ void __launch_bounds__(256) gemm_dual(
    const __nv_bfloat16* __restrict__ A0, const __nv_bfloat16* __restrict__ A1,
    const __nv_bfloat16* __restrict__ B0, const __nv_bfloat16* __restrict__ B1,
    const __nv_bfloat16* __restrict__ C0, const __nv_bfloat16* __restrict__ C1,
    const float* __restrict__ qv, const float* __restrict__ y1,
    float4* __restrict__ part,
    int K, size_t sA, size_t sB)
{
    constexpr unsigned TA = 64 * 128;     // 8 KB
    constexpr unsigned TB = 128 * 128;    // 16 KB
    constexpr unsigned STAGE = 2 * TA + 4 * TB;   // 80 KB

    extern __shared__ char smem[];
    const unsigned sbase = smem_u32(smem);

    const int tid = threadIdx.x;
    const int lid = tid & 31;
    const int wid = tid >> 5;
    const int wm = wid & 1;
    const int wn = wid >> 1;

    const size_t zb = blockIdx.z;
    const __nv_bfloat16* AP[2] = { A0 + zb * sA, A1 + zb * sA };
    const __nv_bfloat16* BP[4] = { B0 + zb * sB, B1 + zb * sB,
                                   C0 + zb * sB, C1 + zb * sB };
    const size_t rm0 = (size_t)blockIdx.y * 64;
    const size_t rn0 = (size_t)blockIdx.x * 128;
    const int NC = K >> 6;

    float c1[2][4][4] = {};
    float c2[2][4][4] = {};

    const int al_r  = lid & 15;
    const int al_k  = (lid >> 4) & 1;
    const int bl_r  = (lid & 7) + ((lid >> 4) << 3);
    const int bl_k  = (lid >> 3) & 1;

    auto load_stage = [&](int st, int ck) {
        const unsigned sdst = sbase + (unsigned)st * STAGE;
        const int k0 = ck << 6;
        #pragma unroll
        for (int sp = 0; sp < 2; sp++) {
            #pragma unroll
            for (int i = 0; i < 2; i++) {
                int idx = i * 256 + tid;
                int row = idx >> 3, g = idx & 7;
                const __nv_bfloat16* gs = AP[sp] + (rm0 + row) * (size_t)K + k0 + g * 8;
                unsigned d = sdst + (unsigned)sp * TA + swz((unsigned)(row * 128 + g * 16));
                CP_ASYNC16(d, gs);
            }
        }
        #pragma unroll
        for (int t4 = 0; t4 < 4; t4++) {
            #pragma unroll
            for (int i = 0; i < 4; i++) {
                int idx = i * 256 + tid;
                int row = idx >> 3, g = idx & 7;
                const __nv_bfloat16* gs = BP[t4] + (rn0 + row) * (size_t)K + k0 + g * 8;
                unsigned d = sdst + 2 * TA + (unsigned)t4 * TB +
                             swz((unsigned)(row * 128 + g * 16));
                CP_ASYNC16(d, gs);
            }
        }
    };

    load_stage(0, 0); CP_COMMIT();

    for (int ck = 0; ck < NC; ck++) {
        if (ck + 1 < NC) {
            load_stage((ck + 1) & 1, ck + 1);
            CP_COMMIT();
            CP_WAIT1();
        } else {
            CP_WAIT0();
        }
        __syncthreads();

        const unsigned sb2 = sbase + (unsigned)(ck & 1) * STAGE;
        #pragma unroll
        for (int ks = 0; ks < 4; ks++) {
            unsigned af[2][2][4];
            #pragma unroll
            for (int sp = 0; sp < 2; sp++)
                #pragma unroll
                for (int mt = 0; mt < 2; mt++) {
                    unsigned addr = sb2 + (unsigned)sp * TA +
                        swz((unsigned)((wm * 32 + mt * 16 + al_r) * 128 + ks * 32 + al_k * 16));
                    ldsm4(af[sp][mt], addr);
                }
            {
                unsigned bf[2][4][2];
                #pragma unroll
                for (int sp = 0; sp < 2; sp++)
                    #pragma unroll
                    for (int np = 0; np < 2; np++) {
                        unsigned r[4];
                        unsigned addr = sb2 + 2 * TA + (unsigned)sp * TB +
                            swz((unsigned)((wn * 32 + np * 16 + bl_r) * 128 + ks * 32 + bl_k * 16));
                        ldsm4(r, addr);
                        bf[sp][2 * np][0] = r[0]; bf[sp][2 * np][1] = r[1];
                        bf[sp][2 * np + 1][0] = r[2]; bf[sp][2 * np + 1][1] = r[3];
                    }
                #pragma unroll
                for (int tm = 0; tm < 3; tm++) {
                    const int i = (tm == 2) ? 1 : 0;
                    const int j = (tm == 1) ? 1 : 0;
                    #pragma unroll
                    for (int mt = 0; mt < 2; mt++)
                        #pragma unroll
                        for (int nt = 0; nt < 4; nt++)
                            mma_bf16(c1[mt][nt], af[i][mt], bf[j][nt]);
                }
            }
            {
                unsigned bf[2][4][2];
                #pragma unroll
                for (int sp = 0; sp < 2; sp++)
                    #pragma unroll
                    for (int np = 0; np < 2; np++) {
                        unsigned r[4];
                        unsigned addr = sb2 + 2 * TA + (unsigned)(2 + sp) * TB +
                            swz((unsigned)((wn * 32 + np * 16 + bl_r) * 128 + ks * 32 + bl_k * 16));
                        ldsm4(r, addr);
                        bf[sp][2 * np][0] = r[0]; bf[sp][2 * np][1] = r[1];
                        bf[sp][2 * np + 1][0] = r[2]; bf[sp][2 * np + 1][1] = r[3];
                    }
                #pragma unroll
                for (int tm = 0; tm < 3; tm++) {
                    const int i = (tm == 2) ? 1 : 0;
                    const int j = (tm == 1) ? 1 : 0;
                    #pragma unroll
                    for (int mt = 0; mt < 2; mt++)
                        #pragma unroll
                        for (int nt = 0; nt < 4; nt++)
                            mma_bf16(c2[mt][nt], af[i][mt], bf[j][nt]);
                }
            }
        }
        __syncthreads();
    }

    // ---- Fused split-softmax epilogue ----
    const int qr = lid >> 2;
    const int qc = (lid & 3) * 2;
    const size_t boff = zb * TT;
    const int tbase = (int)rn0 + wn * 32;

    float2 qvv[4], y1v[4];
    #pragma unroll
    for (int nt = 0; nt < 4; nt++) {
        int t0 = tbase + nt * 8 + qc;
        qvv[nt] = *reinterpret_cast<const float2*>(qv + boff + t0);
        y1v[nt] = *reinterpret_cast<const float2*>(y1 + boff + t0);
    }

    float* sp = reinterpret_cast<float*>(smem);   // [64 rows][4 wn][3] = 3 KB

    #pragma unroll
    for (int mt = 0; mt < 2; mt++) {
        #pragma unroll
        for (int half = 0; half < 2; half++) {
            float sv[8];
            float m = -1e30f;
            #pragma unroll
            for (int nt = 0; nt < 4; nt++) {
                sv[2 * nt]     = c1[mt][nt][2 * half]     + qvv[nt].x;
                sv[2 * nt + 1] = c1[mt][nt][2 * half + 1] + qvv[nt].y;
                m = fmaxf(m, fmaxf(sv[2 * nt], sv[2 * nt + 1]));
            }
            float den = 0.f, num = 0.f;
            #pragma unroll
            for (int nt = 0; nt < 4; nt++) {
                float e0 = __expf(sv[2 * nt] - m);
                float e1 = __expf(sv[2 * nt + 1] - m);
                den += e0 + e1;
                num = fmaf(e0, y1v[nt].x + c2[mt][nt][2 * half], num);
                num = fmaf(e1, y1v[nt].y + c2[mt][nt][2 * half + 1], num);
            }
            // merge across the 4 qc-lanes (lid^1, lid^2)
            #pragma unroll
            for (int o = 1; o <= 2; o <<= 1) {
                float mo = __shfl_xor_sync(0xffffffffu, m, o);
                float dn = __shfl_xor_sync(0xffffffffu, den, o);
                float no = __shfl_xor_sync(0xffffffffu, num, o);
                float mn = fmaxf(m, mo);
                float sa = __expf(m - mn), sb = __expf(mo - mn);
                den = den * sa + dn * sb;
                num = num * sa + no * sb;
                m = mn;
            }
            if ((lid & 3) == 0) {
                int lr = wm * 32 + mt * 16 + qr + half * 8;
                sp[(lr * 4 + wn) * 3 + 0] = m;
                sp[(lr * 4 + wn) * 3 + 1] = den;
                sp[(lr * 4 + wn) * 3 + 2] = num;
            }
        }
    }
    __syncthreads();
    if (tid < 64) {
        float m = -1e30f;
        #pragma unroll
        for (int w = 0; w < 4; w++) m = fmaxf(m, sp[(tid * 4 + w) * 3]);
        float den = 0.f, num = 0.f;
        #pragma unroll
        for (int w = 0; w < 4; w++) {
            float s = __expf(sp[(tid * 4 + w) * 3] - m);
            den = fmaf(sp[(tid * 4 + w) * 3 + 1], s, den);
            num = fmaf(sp[(tid * 4 + w) * 3 + 2], s, num);
        }
        size_t row = zb * RR + rm0 + tid;
        part[row * 4 + blockIdx.x] = make_float4(m, den, num, 0.f);
    }
}

// ---------------------------------------------------------------------------
// Finalize: merge 4 softmax partials per row; out = rd0 + num/den + bs
// ---------------------------------------------------------------------------
__global__ void __launch_bounds__(256) finalize_k(
    const float4* __restrict__ part, const float* __restrict__ rd0,
    const float* __restrict__ bs, float* __restrict__ out)
{
    int i = blockIdx.x * 256 + threadIdx.x;
    float4 p0 = part[(size_t)i * 4 + 0];
    float4 p1 = part[(size_t)i * 4 + 1];
    float4 p2 = part[(size_t)i * 4 + 2];
    float4 p3 = part[(size_t)i * 4 + 3];
    float m = fmaxf(fmaxf(p0.x, p1.x), fmaxf(p2.x, p3.x));
    float s0 = __expf(p0.x - m), s1 = __expf(p1.x - m);
    float s2 = __expf(p2.x - m), s3 = __expf(p3.x - m);
    float den = p0.y * s0 + p1.y * s1 + p2.y * s2 + p3.y * s3;
    float num = p0.z * s0 + p1.z * s1 + p2.z * s2 + p3.z * s3;
    out[i] = rd0[i] + num / den + bs[0];
}

// ---------------------------------------------------------------------------
// fp32 -> 2-way bf16 split (elementwise, vectorized) — for weights
// ---------------------------------------------------------------------------
__global__ void __launch_bounds__(256) split2_k(
    const float4* __restrict__ x, __nv_bfloat16* __restrict__ h,
    __nv_bfloat16* __restrict__ l, int n4)
{
    for (int i = blockIdx.x * blockDim.x + threadIdx.x; i < n4;
         i += gridDim.x * blockDim.x) {
        float4 v = x[i];
        float a[4] = {v.x, v.y, v.z, v.w};
        __nv_bfloat16 hh[4], ll[4];
        #pragma unroll
        for (int k = 0; k < 4; k++) {
            hh[k] = __float2bfloat16(a[k]);
            ll[k] = __float2bfloat16(a[k] - __bfloat162float(hh[k]));
        }
        __nv_bfloat162 p0, p1;
        p0.x = hh[0]; p0.y = hh[1]; p1.x = hh[2]; p1.y = hh[3];
        reinterpret_cast<__nv_bfloat162*>(h)[2 * i] = p0;
        reinterpret_cast<__nv_bfloat162*>(h)[2 * i + 1] = p1;
        p0.x = ll[0]; p0.y = ll[1]; p1.x = ll[2]; p1.y = ll[3];
        reinterpret_cast<__nv_bfloat162*>(l)[2 * i] = p0;
        reinterpret_cast<__nv_bfloat162*>(l)[2 * i + 1] = p1;
    }
}

// ---------------------------------------------------------------------------
// region prep: one CTA per (b,r) row. Writes rf_h/rf_l; computes rd0 = row.Ws0.
// ---------------------------------------------------------------------------
__global__ void __launch_bounds__(256) region_prep_k(
    const float* __restrict__ region, const float* __restrict__ Ws0,
    __nv_bfloat16* __restrict__ rf_h, __nv_bfloat16* __restrict__ rf_l,
    float* __restrict__ rd0)
{
    size_t row = blockIdx.x;
    int t = threadIdx.x;
    float4 a = *reinterpret_cast<const float4*>(region + row * DD + t * 4);
    float4 w = *reinterpret_cast<const float4*>(Ws0 + t * 4);

    __nv_bfloat162 h0, h1, l0, l1;
    h0.x = __float2bfloat16(a.x); h0.y = __float2bfloat16(a.y);
    h1.x = __float2bfloat16(a.z); h1.y = __float2bfloat16(a.w);
    l0.x = __float2bfloat16(a.x - __bfloat162float(h0.x));
    l0.y = __float2bfloat16(a.y - __bfloat162float(h0.y));
    l1.x = __float2bfloat16(a.z - __bfloat162float(h1.x));
    l1.y = __float2bfloat16(a.w - __bfloat162float(h1.y));
    reinterpret_cast<__nv_bfloat162*>(rf_h + row * DD)[2 * t] = h0;
    reinterpret_cast<__nv_bfloat162*>(rf_h + row * DD)[2 * t + 1] = h1;
    reinterpret_cast<__nv_bfloat162*>(rf_l + row * DD)[2 * t] = l0;
    reinterpret_cast<__nv_bfloat162*>(rf_l + row * DD)[2 * t + 1] = l1;

    float p = a.x * w.x + a.y * w.y + a.z * w.z + a.w * w.w;
    __shared__ float red[8];
    #pragma unroll
    for (int o = 16; o; o >>= 1) p += __shfl_xor_sync(0xffffffffu, p, o);
    if ((t & 31) == 0) red[t >> 5] = p;
    __syncthreads();
    if (t == 0) {
        float s = 0.f;
        #pragma unroll
        for (int i = 0; i < 8; i++) s += red[i];
        rd0[row] = s;
    }
}

// ---------------------------------------------------------------------------
// query prep: one CTA per (b,t) row. Writes qe_h/l and qe2_h/l (= qe*Ws2);
// computes qv = row.v and y1 = row.Ws1.
// ---------------------------------------------------------------------------
__global__ void __launch_bounds__(256) query_prep_k(
    const float* __restrict__ query, const float* __restrict__ v,
    const float* __restrict__ Ws1, const float* __restrict__ Ws2,
    __nv_bfloat16* __restrict__ qe_h, __nv_bfloat16* __restrict__ qe_l,
    __nv_bfloat16* __restrict__ qe2_h, __nv_bfloat16* __restrict__ qe2_l,
    float* __restrict__ qv, float* __restrict__ y1)
{
    size_t row = blockIdx.x;
    int t = threadIdx.x;
    float4 a = *reinterpret_cast<const float4*>(query + row * DD + t * 4);
    float4 vv = *reinterpret_cast<const float4*>(v + t * 4);
    float4 w1 = *reinterpret_cast<const float4*>(Ws1 + t * 4);
    float4 w2 = *reinterpret_cast<const float4*>(Ws2 + t * 4);

    __nv_bfloat162 h0, h1, l0, l1;
    h0.x = __float2bfloat16(a.x); h0.y = __float2bfloat16(a.y);
    h1.x = __float2bfloat16(a.z); h1.y = __float2bfloat16(a.w);
    l0.x = __float2bfloat16(a.x - __bfloat162float(h0.x));
    l0.y = __float2bfloat16(a.y - __bfloat162float(h0.y));
    l1.x = __float2bfloat16(a.z - __bfloat162float(h1.x));
    l1.y = __float2bfloat16(a.w - __bfloat162float(h1.y));
    reinterpret_cast<__nv_bfloat162*>(qe_h + row * DD)[2 * t] = h0;
    reinterpret_cast<__nv_bfloat162*>(qe_h + row * DD)[2 * t + 1] = h1;
    reinterpret_cast<__nv_bfloat162*>(qe_l + row * DD)[2 * t] = l0;
    reinterpret_cast<__nv_bfloat162*>(qe_l + row * DD)[2 * t + 1] = l1;

    float b0 = a.x * w2.x, b1 = a.y * w2.y, b2 = a.z * w2.z, b3 = a.w * w2.w;
    h0.x = __float2bfloat16(b0); h0.y = __float2bfloat16(b1);
    h1.x = __float2bfloat16(b2); h1.y = __float2bfloat16(b3);
    l0.x = __float2bfloat16(b0 - __bfloat162float(h0.x));
    l0.y = __float2bfloat16(b1 - __bfloat162float(h0.y));
    l1.x = __float2bfloat16(b2 - __bfloat162float(h1.x));
    l1.y = __float2bfloat16(b3 - __bfloat162float(h1.y));
    reinterpret_cast<__nv_bfloat162*>(qe2_h + row * DD)[2 * t] = h0;
    reinterpret_cast<__nv_bfloat162*>(qe2_h + row * DD)[2 * t + 1] = h1;
    reinterpret_cast<__nv_bfloat162*>(qe2_l + row * DD)[2 * t] = l0;
    reinterpret_cast<__nv_bfloat162*>(qe2_l + row * DD)[2 * t + 1] = l1;

    float p = a.x * vv.x + a.y * vv.y + a.z * vv.z + a.w * vv.w;
    float q = a.x * w1.x + a.y * w1.y + a.z * w1.z + a.w * w1.w;
    __shared__ float red[16];
    #pragma unroll
    for (int o = 16; o; o >>= 1) {
        p += __shfl_xor_sync(0xffffffffu, p, o);
        q += __shfl_xor_sync(0xffffffffu, q, o);
    }
    if ((t & 31) == 0) { red[t >> 5] = p; red[8 + (t >> 5)] = q; }
    __syncthreads();
    if (t == 0) {
        float s = 0.f, s2 = 0.f;
        #pragma unroll
        for (int i = 0; i < 8; i++) { s += red[i]; s2 += red[8 + i]; }
        qv[row] = s;
        y1[row] = s2;
    }
}

// ---------------------------------------------------------------------------
// v[d] = sum_h Wq[d,h] * br[h]
// ---------------------------------------------------------------------------
__global__ void __launch_bounds__(256) matvec_k(
    const float* __restrict__ W, const float* __restrict__ b,
    float* __restrict__ v, int H)
{
    const float* row = W + (size_t)blockIdx.x * H;
    int t = threadIdx.x;
    float p = 0.f;
    for (int h = t * 4; h < H; h += 1024) {
        float4 wv = *reinterpret_cast<const float4*>(row + h);
        float4 bv = *reinterpret_cast<const float4*>(b + h);
        p = fmaf(wv.x, bv.x, p); p = fmaf(wv.y, bv.y, p);
        p = fmaf(wv.z, bv.z, p); p = fmaf(wv.w, bv.w, p);
    }
    __shared__ float red[8];
    #pragma unroll
    for (int o = 16; o; o >>= 1) p += __shfl_xor_sync(0xffffffffu, p, o);
    if ((t & 31) == 0) red[t >> 5] = p;
    __syncthreads();
    if (t == 0) {
        float s = 0.f;
        #pragma unroll
        for (int i = 0; i < 8; i++) s += red[i];
        v[blockIdx.x] = s;
    }
}

// ---------------------------------------------------------------------------
extern "C" void kernel_launch(void* const* d_in, const int* in_sizes, int n_in,
                              void* d_out, int out_size)
{
    const float* region = (const float*)d_in[0];
    const float* query  = (const float*)d_in[1];
    const float* Wr     = (const float*)d_in[2];
    const float* br     = (const float*)d_in[3];
    const float* Wq     = (const float*)d_in[4];
    const float* bq     = (const float*)d_in[5];
    const float* Ws     = (const float*)d_in[6];
    const float* bs     = (const float*)d_in[7];
    float* out = (float*)d_out;
    (void)bq;  // softmax-invariant terms drop out

    __nv_bfloat16 *Wr_h, *Wr_l, *Wq_h, *Wq_l, *M2_h, *M2_l;
    __nv_bfloat16 *rf_h, *rf_l, *qe_h, *qe_l, *qe2_h, *qe2_l, *Nt_h, *Nt_l;
    float4 *partb;
    float *v, *qv, *y1, *rd0;
    cudaGetSymbolAddress((void**)&Wr_h, g_Wr_h);
    cudaGetSymbolAddress((void**)&Wr_l, g_Wr_l);
    cudaGetSymbolAddress((void**)&Wq_h, g_Wq_h);
    cudaGetSymbolAddress((void**)&Wq_l, g_Wq_l);
    cudaGetSymbolAddress((void**)&M2_h, g_M2_h);
    cudaGetSymbolAddress((void**)&M2_l, g_M2_l);
    cudaGetSymbolAddress((void**)&rf_h, g_rf_h);
    cudaGetSymbolAddress((void**)&rf_l, g_rf_l);
    cudaGetSymbolAddress((void**)&qe_h, g_qe_h);
    cudaGetSymbolAddress((void**)&qe_l, g_qe_l);
    cudaGetSymbolAddress((void**)&qe2_h, g_qe2_h);
    cudaGetSymbolAddress((void**)&qe2_l, g_qe2_l);
    cudaGetSymbolAddress((void**)&Nt_h, g_Nt_h);
    cudaGetSymbolAddress((void**)&Nt_l, g_Nt_l);
    cudaGetSymbolAddress((void**)&partb, g_part);
    cudaGetSymbolAddress((void**)&v, g_v);
    cudaGetSymbolAddress((void**)&qv, g_qv);
    cudaGetSymbolAddress((void**)&y1, g_y1);
    cudaGetSymbolAddress((void**)&rd0, g_rd0);

    const int SMEM1 = 3 * (2 * 8192 + 2 * 16384);       // 147456 (3-stage, 48KB)
    const int SMEMD = 2 * (2 * 8192 + 4 * 16384);       // 163840 (2-stage, 80KB)
    cudaFuncSetAttribute(gemm_mma1, cudaFuncAttributeMaxDynamicSharedMemorySize, SMEM1);
    cudaFuncSetAttribute(gemm_dual, cudaFuncAttributeMaxDynamicSharedMemorySize, SMEMD);

    // 1) weight splits + bias matvec
    split2_k<<<512, 256>>>((const float4*)Wr, Wr_h, Wr_l, DD * HH / 4);
    split2_k<<<512, 256>>>((const float4*)Wq, Wq_h, Wq_l, DD * HH / 4);
    matvec_k<<<DD, 256>>>(Wq, br, v, HH);
    // 2) fused activation prep (single pass over region and query)
    region_prep_k<<<BB * RR, 256>>>(region, Ws, rf_h, rf_l, rd0);
    query_prep_k<<<BB * TT, 256>>>(query, v, Ws + DD, Ws + 2 * DD,
                                   qe_h, qe_l, qe2_h, qe2_l, qv, y1);
    // 3) M2[d,e] = sum_h Wr[d,h] Wq[e,h]  (e contiguous), split output
    gemm_mma1<<<dim3(DD / 128, DD / 64, 1), 256, SMEM1>>>(
        Wr_h, Wr_l, Wq_h, Wq_l, M2_h, M2_l, HH, 0, 0, 0, DD);
    // 4) Nt[b][t,d] = sum_e qe[b,t,e] M2[d,e]  (d contiguous), split output
    gemm_mma1<<<dim3(DD / 128, TT / 64, BB), 256, SMEM1>>>(
        qe_h, qe_l, M2_h, M2_l, Nt_h, Nt_l,
        DD, (size_t)TT * DD, 0, (size_t)TT * DD, DD);
    // 5) dual GEMM with fused split-softmax epilogue -> partials
    gemm_dual<<<dim3(TT / 128, RR / 64, BB), 256, SMEMD>>>(
        rf_h, rf_l, Nt_h, Nt_l, qe2_h, qe2_l, qv, y1, partb,
        DD, (size_t)RR * DD, (size_t)TT * DD);
    // 6) finalize: merge partials -> out
    finalize_k<<<BB * RR / 256, 256>>>(partb, rd0, bs, out);
}